// round 1
// baseline (speedup 1.0000x reference)
#include <cuda_runtime.h>

// ---------------------------------------------------------------------------
// SpectralConv2d (FNO) on GB300.
// B=8, CIN=COUT=64, H=W=256, M1=M2=32. Two branches (x and x^T).
// Strategy: truncated DFT sandwiches instead of full FFTs.
//   tw[t] = exp(-2*pi*i*t/256)  (single 256-entry table, double-precision init)
// Stage 1: T[ch,h,k2]  = sum_w x[*,h,w] * tw[k2*w]                (k2 in 0..31)
// Stage 2: XF[ch,j,k2] = sum_h T[ch,h,k2] * tw[k1(j)*h]           (j in 0..63)
//          k1(j) = j (j<32)  or  192+j (j>=32  ->  rows 224..255)
// Stage 3: Y[b,o,j,k2] = sum_i XF[b,i,j,k2] * (w1|w2)[i,o,jw,k2]  (complex)
// Stage 4: Z[ch,h,k2]  = sum_j Y[ch,j,k2] * conj(tw[k1(j)*h])
// Stage 5: out[ch,h,w] = ( Zr[h,0] + 2*sum_{k2=1..31} ( Zr*twr + Zi*twi )[k2*w] ) / 65536
// ---------------------------------------------------------------------------

namespace {
constexpr int Bv  = 8;
constexpr int Cv  = 64;
constexpr int Hv  = 256;
constexpr int Wv  = 256;
constexpr int M2v = 32;
constexpr int K1v = 64;            // 2*M1
constexpr int NCH = Bv * Cv;       // 512
constexpr int HWv = Hv * Wv;       // 65536
}

// twiddle table: tw[t] = exp(-2*pi*i*t/256)
__device__ float g_twr[256];
__device__ float g_twi[256];

// scratch (zero-initialized device globals; allocation-free per harness rules)
__device__ float g_T [NCH * Hv  * M2v * 2];   // 33.5 MB
__device__ float g_XF[NCH * K1v * M2v * 2];   //  8.4 MB
__device__ float g_Y [NCH * K1v * M2v * 2];   //  8.4 MB
__device__ float g_Z [NCH * Hv  * M2v * 2];   // 33.5 MB

__global__ void k_init_tw() {
    int t = threadIdx.x;
    double s, c;
    sincospi(-2.0 * (double)t / 256.0, &s, &c);
    g_twr[t] = (float)c;
    g_twi[t] = (float)s;
}

// Stage 1: one block per (ch,h) row. trans=1 reads x[ch, w, h] (x^T branch).
__global__ void k_fwd_w(const float* __restrict__ x, int trans) {
    __shared__ float sx[256];
    __shared__ float str[256], sti[256];
    __shared__ float sre[256], sim[256];
    int t   = threadIdx.x;
    int row = blockIdx.x;            // ch*256 + h
    int ch  = row >> 8;
    int h   = row & 255;
    const float* xp = x + (size_t)ch * HWv + (trans ? h : h * Wv);
    int stride = trans ? Wv : 1;
    sx[t]  = xp[t * stride];
    str[t] = g_twr[t];
    sti[t] = g_twi[t];
    __syncthreads();

    int k2    = t & 31;
    int chunk = t >> 5;              // 0..7, each handles 32 w's
    float ar = 0.f, ai = 0.f;
    int wbase = chunk * 32;
#pragma unroll
    for (int i = 0; i < 32; i++) {
        int w   = wbase + i;
        float xv = sx[w];
        int tt  = (k2 * w) & 255;
        ar = fmaf(xv, str[tt], ar);
        ai = fmaf(xv, sti[tt], ai);
    }
    sre[t] = ar;
    sim[t] = ai;
    __syncthreads();
    for (int off = 128; off >= 32; off >>= 1) {
        if (t < off) { sre[t] += sre[t + off]; sim[t] += sim[t + off]; }
        __syncthreads();
    }
    if (t < 32) {
        float* T = g_T + ((size_t)row * 32 + t) * 2;
        T[0] = sre[t];
        T[1] = sim[t];
    }
}

// Stage 2: one block per channel. 2048 outputs (64 j x 32 k2), 8 j's per thread.
__global__ void k_fwd_h() {
    __shared__ float str[256], sti[256];
    int t  = threadIdx.x;
    int ch = blockIdx.x;
    str[t] = g_twr[t];
    sti[t] = g_twi[t];
    __syncthreads();

    int k2 = t & 31;
    int jb = t >> 5;                 // 0..7
    const float2* T  = (const float2*)(g_T  + (size_t)ch * Hv  * 32 * 2);
    float2*       XF = (float2*)      (g_XF + (size_t)ch * K1v * 32 * 2);
#pragma unroll
    for (int jj = 0; jj < 8; jj++) {
        int j  = jb * 8 + jj;
        int k1 = (j < 32) ? j : (192 + j);
        float ar = 0.f, ai = 0.f;
        for (int hh = 0; hh < 256; hh++) {
            float2 tv = T[hh * 32 + k2];
            int tt  = (k1 * hh) & 255;
            float er = str[tt], ei = sti[tt];
            ar += tv.x * er - tv.y * ei;
            ai += tv.x * ei + tv.y * er;
        }
        XF[j * 32 + k2] = make_float2(ar, ai);
    }
}

// Stage 3: one block per (j,k2); 512 threads = (b,o) pairs; reduce over cin.
__global__ void k_modes(const float* __restrict__ wAr, const float* __restrict__ wAi,
                        const float* __restrict__ wBr, const float* __restrict__ wBi) {
    int jk = blockIdx.x;             // 0..2047
    int j  = jk >> 5;
    int k2 = jk & 31;
    int t  = threadIdx.x;            // 0..511
    int b  = t >> 6;
    int o  = t & 63;

    const float* wr;
    const float* wi;
    int jw;
    if (j < 32) { wr = wAr; wi = wAi; jw = j; }
    else        { wr = wBr; wi = wBi; jw = j - 32; }

    float ar = 0.f, ai = 0.f;
#pragma unroll 4
    for (int i = 0; i < 64; i++) {
        float2 xv = *(const float2*)(g_XF + ((((size_t)(b * 64 + i)) * 64 + j) * 32 + k2) * 2);
        int widx  = ((i * 64 + o) * 32 + jw) * 32 + k2;
        float wre = wr[widx];
        float wim = wi[widx];
        ar += xv.x * wre - xv.y * wim;
        ai += xv.x * wim + xv.y * wre;
    }
    float2* Y = (float2*)(g_Y + ((((size_t)(b * 64 + o)) * 64 + j) * 32 + k2) * 2);
    *Y = make_float2(ar, ai);
}

// Stage 4: one block per channel; Y tile staged in smem; 32 h's per thread.
__global__ void k_inv_h() {
    __shared__ float  str[256], sti[256];
    __shared__ float2 sy[K1v * 32];  // 16 KB
    int t  = threadIdx.x;
    int ch = blockIdx.x;
    str[t] = g_twr[t];
    sti[t] = g_twi[t];
    const float2* Y = (const float2*)(g_Y + (size_t)ch * K1v * 32 * 2);
    for (int i = t; i < K1v * 32; i += 256) sy[i] = Y[i];
    __syncthreads();

    int k2 = t & 31;
    int hb = t >> 5;                 // 0..7
    float2* Z = (float2*)(g_Z + (size_t)ch * Hv * 32 * 2);
    for (int hh = 0; hh < 32; hh++) {
        int h = hb * 32 + hh;
        float ar = 0.f, ai = 0.f;
#pragma unroll
        for (int j = 0; j < 64; j++) {
            int k1 = (j < 32) ? j : (192 + j);
            float2 yv = sy[j * 32 + k2];
            int tt  = (k1 * h) & 255;
            float er = str[tt];
            float ei = -sti[tt];     // conj -> e^{+i*theta}
            ar += yv.x * er - yv.y * ei;
            ai += yv.x * ei + yv.y * er;
        }
        Z[h * 32 + k2] = make_float2(ar, ai);
    }
}

// Stage 5: one block per (ch,h) row; thread = w.
__global__ void k_inv_w(float* __restrict__ out) {
    __shared__ float zr[32], zi[32];
    __shared__ float str[256], sti[256];
    int t   = threadIdx.x;
    int row = blockIdx.x;            // ch*256 + h
    const float2* Z = (const float2*)(g_Z + (size_t)row * 32 * 2);
    if (t < 32) {
        float2 z = Z[t];
        zr[t] = z.x;
        zi[t] = z.y;
    }
    str[t] = g_twr[t];
    sti[t] = g_twi[t];
    __syncthreads();

    int w = t;
    float acc2 = 0.f;
#pragma unroll
    for (int k2 = 1; k2 < 32; k2++) {
        int tt = (k2 * w) & 255;
        // Re(Z * conj(tw)) = Zr*twr + Zi*twi   (twi = -sin)
        acc2 = fmaf(zr[k2], str[tt], acc2);
        acc2 = fmaf(zi[k2], sti[tt], acc2);
    }
    out[(size_t)row * Wv + w] = (zr[0] + 2.f * acc2) * (1.f / 65536.f);
}

extern "C" void kernel_launch(void* const* d_in, const int* in_sizes, int n_in,
                              void* d_out, int out_size) {
    const float* x   = (const float*)d_in[0];
    const float* w1r = (const float*)d_in[1];
    const float* w1i = (const float*)d_in[2];
    const float* w2r = (const float*)d_in[3];
    const float* w2i = (const float*)d_in[4];
    const float* w3r = (const float*)d_in[5];
    const float* w3i = (const float*)d_in[6];
    const float* w4r = (const float*)d_in[7];
    const float* w4i = (const float*)d_in[8];
    float* out = (float*)d_out;

    k_init_tw<<<1, 256>>>();

    // ---- branch x ----
    k_fwd_w<<<NCH * Hv, 256>>>(x, 0);
    k_fwd_h<<<NCH, 256>>>();
    k_modes<<<K1v * 32, 512>>>(w1r, w1i, w2r, w2i);
    k_inv_h<<<NCH, 256>>>();
    k_inv_w<<<NCH * Hv, 256>>>(out);

    // ---- branch x^T ----
    k_fwd_w<<<NCH * Hv, 256>>>(x, 1);
    k_fwd_h<<<NCH, 256>>>();
    k_modes<<<K1v * 32, 512>>>(w3r, w3i, w4r, w4i);
    k_inv_h<<<NCH, 256>>>();
    k_inv_w<<<NCH * Hv, 256>>>(out + (size_t)NCH * HWv);
}

// round 2
// speedup vs baseline: 3.8855x; 3.8855x over previous
#include <cuda_runtime.h>

// ---------------------------------------------------------------------------
// SpectralConv2d (FNO), GEMM-formulated. B=8, C=64, H=W=256, M1=M2=32.
// tw[t] = exp(-2*pi*i*t/256): twr=cos, twi=-sin.
// S1: T[ch,r,c]   = sum_k X[...] * E1[k][c]      (r=h,k=w br1; r=w,k=h br2)
// S2: XF[ch,j,k2] = sum_h T[ch,h,*] (x) tw[k1(j)h]       complex
// S3: Y[b,o,j,k2] = sum_i XF[b,i,j,k2] * Wt[jk][i][o]    complex (Wt pre-transposed)
// S4: Z[ch,h,*]   = sum_j Y[ch,j,*] (x) conj(tw[k1(j)h]) complex
// S5: out[ch,h,w] = sum_c Z[ch,h,c] * F[c][w]            (halfcomplex irfft fold)
// ---------------------------------------------------------------------------

namespace {
constexpr int NCH = 512;           // B*C
}

__device__ float g_twr[256];
__device__ float g_twi[256];
__device__ float g_E1[256 * 64];             // forward DFT matrix (k x [2*k2+ri])
__device__ float g_F [64 * 256];             // inverse halfcomplex fold matrix
__device__ float g_T [NCH * 256 * 64];       // 33.5 MB
__device__ float g_XF[NCH * 64 * 32 * 2];    //  8.4 MB
__device__ float g_Y [NCH * 64 * 32 * 2];    //  8.4 MB
__device__ float g_Z [NCH * 256 * 64];       // 33.5 MB
__device__ float g_Wt[2048 * 4096 * 2];      // 67 MB  [jk][i*64+o][ri]

// ---------------- init: twiddles + DFT matrices -----------------------------
__global__ void k_init_mats() {
    int bid = blockIdx.x;
    int t   = threadIdx.x;
    if (bid < 256) {                      // E1 row w = bid
        if (t < 64) {
            int w = bid, k2 = t >> 1, ri = t & 1;
            int ang = (k2 * w) & 255;
            double s, c;
            sincospi(-2.0 * (double)ang / 256.0, &s, &c);
            g_E1[w * 64 + t] = (float)(ri ? s : c);
        }
    } else if (bid < 320) {               // F row c = bid-256, thread = w
        int cc = bid - 256;
        int w  = t;
        int k2 = cc >> 1, ri = cc & 1;
        int ang = (k2 * w) & 255;
        double s, c;
        sincospi(-2.0 * (double)ang / 256.0, &s, &c);
        const float sc = 1.0f / 65536.0f;
        float v;
        if (k2 == 0) v = ri ? 0.0f : sc;
        else         v = 2.0f * sc * (float)(ri ? s : c);
        g_F[cc * 256 + w] = v;
    } else {                              // twiddle tables
        double s, c;
        sincospi(-2.0 * (double)t / 256.0, &s, &c);
        g_twr[t] = (float)c;
        g_twi[t] = (float)s;
    }
}

// ---------------- weight transpose: w[i,o,jw,k2] -> Wt[jk][io]{r,i} ---------
__global__ __launch_bounds__(256) void k_wt(const float* __restrict__ wAr,
                                            const float* __restrict__ wAi,
                                            const float* __restrict__ wBr,
                                            const float* __restrict__ wBi) {
    __shared__ float tr[32][33];
    __shared__ float ti[32][33];
    int t   = threadIdx.x;
    int bid = blockIdx.x;
    int j   = bid >> 7;          // 0..63
    int iot = bid & 127;         // io tile (32 io's each)
    const float* wr; const float* wi; int jw;
    if (j < 32) { wr = wAr; wi = wAi; jw = j; }
    else        { wr = wBr; wi = wBi; jw = j - 32; }
    int lk  = t & 31;
    int lr  = t >> 5;            // 0..7
#pragma unroll
    for (int p = 0; p < 4; p++) {
        int io = lr + p * 8;
        size_t src = ((size_t)(iot * 32 + io)) * 1024 + jw * 32 + lk;
        tr[io][lk] = wr[src];
        ti[io][lk] = wi[src];
    }
    __syncthreads();
#pragma unroll
    for (int p = 0; p < 4; p++) {
        int k2 = lr + p * 8;
        size_t dst = (((size_t)(j * 32 + k2)) * 4096 + iot * 32 + lk) * 2;
        *(float2*)(g_Wt + dst) = make_float2(tr[lk][k2], ti[lk][k2]);
    }
}

// ---------------- stage 1: truncated forward DFT (GEMM) ---------------------
// block = (ch, tile of 64 output rows); K=256 chunked by 64.
__global__ __launch_bounds__(256) void k_s1(const float* __restrict__ x, int trans) {
    __shared__ float xs[64 * 65];
    __shared__ float es[64 * 64];
    int t    = threadIdx.x;
    int bid  = blockIdx.x;
    int ch   = bid >> 2;
    int tile = bid & 3;
    const float* xc = x + (size_t)ch * 65536;
    int r  = t >> 2;             // output row within tile
    int cg = t & 3;              // col group (16 cols)
    float acc[16];
#pragma unroll
    for (int i = 0; i < 16; i++) acc[i] = 0.f;

    for (int kc = 0; kc < 4; kc++) {
        const float4* esrc = (const float4*)(g_E1 + kc * 4096);
        float4* edst = (float4*)es;
#pragma unroll
        for (int q = 0; q < 4; q++) edst[q * 256 + t] = esrc[q * 256 + t];
#pragma unroll
        for (int q = 0; q < 16; q++) {
            int flat = q * 256 + t;
            int i1 = flat >> 6, i2 = flat & 63;
            if (!trans) xs[i2 * 65 + i1] = xc[(tile * 64 + i1) * 256 + kc * 64 + i2];
            else        xs[i1 * 65 + i2] = xc[(kc * 64 + i1) * 256 + tile * 64 + i2];
        }
        __syncthreads();
#pragma unroll 8
        for (int kk = 0; kk < 64; kk++) {
            float xv = xs[kk * 65 + r];
            const float4* ek = (const float4*)(es + kk * 64 + cg * 16);
            float4 e0 = ek[0], e1 = ek[1], e2 = ek[2], e3 = ek[3];
            acc[0]  = fmaf(xv, e0.x, acc[0]);  acc[1]  = fmaf(xv, e0.y, acc[1]);
            acc[2]  = fmaf(xv, e0.z, acc[2]);  acc[3]  = fmaf(xv, e0.w, acc[3]);
            acc[4]  = fmaf(xv, e1.x, acc[4]);  acc[5]  = fmaf(xv, e1.y, acc[5]);
            acc[6]  = fmaf(xv, e1.z, acc[6]);  acc[7]  = fmaf(xv, e1.w, acc[7]);
            acc[8]  = fmaf(xv, e2.x, acc[8]);  acc[9]  = fmaf(xv, e2.y, acc[9]);
            acc[10] = fmaf(xv, e2.z, acc[10]); acc[11] = fmaf(xv, e2.w, acc[11]);
            acc[12] = fmaf(xv, e3.x, acc[12]); acc[13] = fmaf(xv, e3.y, acc[13]);
            acc[14] = fmaf(xv, e3.z, acc[14]); acc[15] = fmaf(xv, e3.w, acc[15]);
        }
        __syncthreads();
    }
    float4* dst = (float4*)(g_T + (((size_t)ch * 256) + tile * 64 + r) * 64 + cg * 16);
    dst[0] = make_float4(acc[0], acc[1], acc[2], acc[3]);
    dst[1] = make_float4(acc[4], acc[5], acc[6], acc[7]);
    dst[2] = make_float4(acc[8], acc[9], acc[10], acc[11]);
    dst[3] = make_float4(acc[12], acc[13], acc[14], acc[15]);
}

// ---------------- stage 2: forward DFT over h (complex) ---------------------
// block per ch; thread = (j, k2-group of 8).
__global__ __launch_bounds__(256) void k_s2() {
    __shared__ float sT[64 * 64];
    __shared__ float str[256], sti[256];
    int t  = threadIdx.x;
    int ch = blockIdx.x;
    str[t] = g_twr[t];
    sti[t] = g_twi[t];
    int j  = t >> 2;
    int cg = t & 3;
    int k1 = (j < 32) ? j : (192 + j);
    float ar[8], ai[8];
#pragma unroll
    for (int i = 0; i < 8; i++) { ar[i] = 0.f; ai[i] = 0.f; }

    for (int hc = 0; hc < 4; hc++) {
        __syncthreads();
        const float4* src = (const float4*)(g_T + (((size_t)ch * 256) + hc * 64) * 64);
        float4* dst = (float4*)sT;
#pragma unroll
        for (int q = 0; q < 4; q++) dst[q * 256 + t] = src[q * 256 + t];
        __syncthreads();
#pragma unroll 4
        for (int hh = 0; hh < 64; hh++) {
            int h   = hc * 64 + hh;
            int idx = (k1 * h) & 255;
            float er = str[idx], ei = sti[idx];
            const float4* Tp = (const float4*)(sT + hh * 64 + cg * 16);
            float4 a = Tp[0], b = Tp[1], c = Tp[2], d = Tp[3];
            ar[0] = fmaf(a.x, er, ar[0]); ar[0] = fmaf(-a.y, ei, ar[0]);
            ai[0] = fmaf(a.x, ei, ai[0]); ai[0] = fmaf( a.y, er, ai[0]);
            ar[1] = fmaf(a.z, er, ar[1]); ar[1] = fmaf(-a.w, ei, ar[1]);
            ai[1] = fmaf(a.z, ei, ai[1]); ai[1] = fmaf( a.w, er, ai[1]);
            ar[2] = fmaf(b.x, er, ar[2]); ar[2] = fmaf(-b.y, ei, ar[2]);
            ai[2] = fmaf(b.x, ei, ai[2]); ai[2] = fmaf( b.y, er, ai[2]);
            ar[3] = fmaf(b.z, er, ar[3]); ar[3] = fmaf(-b.w, ei, ar[3]);
            ai[3] = fmaf(b.z, ei, ai[3]); ai[3] = fmaf( b.w, er, ai[3]);
            ar[4] = fmaf(c.x, er, ar[4]); ar[4] = fmaf(-c.y, ei, ar[4]);
            ai[4] = fmaf(c.x, ei, ai[4]); ai[4] = fmaf( c.y, er, ai[4]);
            ar[5] = fmaf(c.z, er, ar[5]); ar[5] = fmaf(-c.w, ei, ar[5]);
            ai[5] = fmaf(c.z, ei, ai[5]); ai[5] = fmaf( c.w, er, ai[5]);
            ar[6] = fmaf(d.x, er, ar[6]); ar[6] = fmaf(-d.y, ei, ar[6]);
            ai[6] = fmaf(d.x, ei, ai[6]); ai[6] = fmaf( d.y, er, ai[6]);
            ar[7] = fmaf(d.z, er, ar[7]); ar[7] = fmaf(-d.w, ei, ar[7]);
            ai[7] = fmaf(d.z, ei, ai[7]); ai[7] = fmaf( d.w, er, ai[7]);
        }
    }
    float4* dst = (float4*)(g_XF + ((((size_t)ch * 64) + j) * 32 + cg * 8) * 2);
    dst[0] = make_float4(ar[0], ai[0], ar[1], ai[1]);
    dst[1] = make_float4(ar[2], ai[2], ar[3], ai[3]);
    dst[2] = make_float4(ar[4], ai[4], ar[5], ai[5]);
    dst[3] = make_float4(ar[6], ai[6], ar[7], ai[7]);
}

// ---------------- stage 3: mode mix (batched complex GEMM) ------------------
// block per (j,k2); 512 threads = (b,o); Wt staged in smem (coalesced).
__global__ __launch_bounds__(512) void k_s3() {
    __shared__ float sw[64 * 64 * 2];   // 32 KB
    __shared__ float sx[512 * 2];       // 4 KB
    int t  = threadIdx.x;
    int jk = blockIdx.x;
    int j  = jk >> 5;
    int k2 = jk & 31;
    const float4* wsrc = (const float4*)(g_Wt + (size_t)jk * 8192);
    float4* wdst = (float4*)sw;
#pragma unroll
    for (int q = 0; q < 4; q++) wdst[q * 512 + t] = wsrc[q * 512 + t];
    int b = t >> 6;
    int i = t & 63;
    ((float2*)sx)[t] = *(const float2*)(g_XF + ((((size_t)(b * 64 + i)) * 64 + j) * 32 + k2) * 2);
    __syncthreads();
    int o = t & 63;
    float ar = 0.f, ai = 0.f;
    const float2* swp = (const float2*)sw;
    const float2* sxp = (const float2*)sx;
#pragma unroll 8
    for (int ii = 0; ii < 64; ii++) {
        float2 xv = sxp[b * 64 + ii];
        float2 wv = swp[ii * 64 + o];
        ar = fmaf(xv.x, wv.x, ar); ar = fmaf(-xv.y, wv.y, ar);
        ai = fmaf(xv.x, wv.y, ai); ai = fmaf( xv.y, wv.x, ai);
    }
    *(float2*)(g_Y + ((((size_t)(b * 64 + o)) * 64 + j) * 32 + k2) * 2) = make_float2(ar, ai);
}

// ---------------- stage 4: inverse DFT over h (complex) ---------------------
// block = (ch, h-tile of 64); thread = (hh, k2-group of 8).
__global__ __launch_bounds__(256) void k_s4() {
    __shared__ float sY[64 * 64];
    __shared__ float str[256], sti[256];
    int t   = threadIdx.x;
    int bid = blockIdx.x;
    int ch  = bid >> 2;
    int ht  = bid & 3;
    str[t] = g_twr[t];
    sti[t] = g_twi[t];
    const float4* src = (const float4*)(g_Y + (size_t)ch * 4096);
    float4* dst = (float4*)sY;
#pragma unroll
    for (int q = 0; q < 4; q++) dst[q * 256 + t] = src[q * 256 + t];
    __syncthreads();
    int hh = t >> 2;
    int cg = t & 3;
    int h  = ht * 64 + hh;
    float zr[8], zi[8];
#pragma unroll
    for (int i = 0; i < 8; i++) { zr[i] = 0.f; zi[i] = 0.f; }
#pragma unroll 4
    for (int j = 0; j < 64; j++) {
        int k1  = (j < 32) ? j : (192 + j);
        int idx = (k1 * h) & 255;
        float c = str[idx], s = sti[idx];
        const float4* Yp = (const float4*)(sY + j * 64 + cg * 16);
        float4 a = Yp[0], b2 = Yp[1], c2 = Yp[2], d = Yp[3];
        // Zr += Yr*c + Yi*s ; Zi += Yi*c - Yr*s
        zr[0] = fmaf(a.x, c, zr[0]);  zr[0] = fmaf(a.y, s, zr[0]);
        zi[0] = fmaf(a.y, c, zi[0]);  zi[0] = fmaf(-a.x, s, zi[0]);
        zr[1] = fmaf(a.z, c, zr[1]);  zr[1] = fmaf(a.w, s, zr[1]);
        zi[1] = fmaf(a.w, c, zi[1]);  zi[1] = fmaf(-a.z, s, zi[1]);
        zr[2] = fmaf(b2.x, c, zr[2]); zr[2] = fmaf(b2.y, s, zr[2]);
        zi[2] = fmaf(b2.y, c, zi[2]); zi[2] = fmaf(-b2.x, s, zi[2]);
        zr[3] = fmaf(b2.z, c, zr[3]); zr[3] = fmaf(b2.w, s, zr[3]);
        zi[3] = fmaf(b2.w, c, zi[3]); zi[3] = fmaf(-b2.z, s, zi[3]);
        zr[4] = fmaf(c2.x, c, zr[4]); zr[4] = fmaf(c2.y, s, zr[4]);
        zi[4] = fmaf(c2.y, c, zi[4]); zi[4] = fmaf(-c2.x, s, zi[4]);
        zr[5] = fmaf(c2.z, c, zr[5]); zr[5] = fmaf(c2.w, s, zr[5]);
        zi[5] = fmaf(c2.w, c, zi[5]); zi[5] = fmaf(-c2.z, s, zi[5]);
        zr[6] = fmaf(d.x, c, zr[6]);  zr[6] = fmaf(d.y, s, zr[6]);
        zi[6] = fmaf(d.y, c, zi[6]);  zi[6] = fmaf(-d.x, s, zi[6]);
        zr[7] = fmaf(d.z, c, zr[7]);  zr[7] = fmaf(d.w, s, zr[7]);
        zi[7] = fmaf(d.w, c, zi[7]);  zi[7] = fmaf(-d.z, s, zi[7]);
    }
    float4* zdst = (float4*)(g_Z + (((size_t)ch * 256) + h) * 64 + cg * 16);
    zdst[0] = make_float4(zr[0], zi[0], zr[1], zi[1]);
    zdst[1] = make_float4(zr[2], zi[2], zr[3], zi[3]);
    zdst[2] = make_float4(zr[4], zi[4], zr[5], zi[5]);
    zdst[3] = make_float4(zr[6], zi[6], zr[7], zi[7]);
}

// ---------------- stage 5: halfcomplex inverse DFT over w (GEMM) ------------
// block = (ch, h-tile 4, w-tile 4); 64x64 tile, K=64.
__global__ __launch_bounds__(256) void k_s5(float* __restrict__ out) {
    __shared__ float zs[64 * 65];
    __shared__ float fs[64 * 64];
    int t   = threadIdx.x;
    int bid = blockIdx.x;
    int ch  = bid >> 4;
    int ht  = (bid >> 2) & 3;
    int wt  = bid & 3;
    // load F chunk (cols wt*64..+64) via float4
    const float4* F4 = (const float4*)g_F;
    float4* fs4 = (float4*)fs;
#pragma unroll
    for (int q = 0; q < 4; q++) {
        int id  = q * 256 + t;
        int row = id >> 4, c4 = id & 15;
        fs4[row * 16 + c4] = F4[row * 64 + wt * 16 + c4];
    }
    // load Z tile transposed into zs[c][h]
#pragma unroll
    for (int q = 0; q < 16; q++) {
        int flat = q * 256 + t;
        int h = flat >> 6, c = flat & 63;
        zs[c * 65 + h] = g_Z[(((size_t)ch * 256) + ht * 64 + h) * 64 + c];
    }
    __syncthreads();
    int rg = t >> 4;
    int wg = t & 15;
    float acc[16];
#pragma unroll
    for (int i = 0; i < 16; i++) acc[i] = 0.f;
#pragma unroll 8
    for (int c = 0; c < 64; c++) {
        float z0 = zs[c * 65 + rg * 4 + 0];
        float z1 = zs[c * 65 + rg * 4 + 1];
        float z2 = zs[c * 65 + rg * 4 + 2];
        float z3 = zs[c * 65 + rg * 4 + 3];
        float4 f = *(const float4*)(fs + c * 64 + wg * 4);
        acc[0]  = fmaf(z0, f.x, acc[0]);  acc[1]  = fmaf(z0, f.y, acc[1]);
        acc[2]  = fmaf(z0, f.z, acc[2]);  acc[3]  = fmaf(z0, f.w, acc[3]);
        acc[4]  = fmaf(z1, f.x, acc[4]);  acc[5]  = fmaf(z1, f.y, acc[5]);
        acc[6]  = fmaf(z1, f.z, acc[6]);  acc[7]  = fmaf(z1, f.w, acc[7]);
        acc[8]  = fmaf(z2, f.x, acc[8]);  acc[9]  = fmaf(z2, f.y, acc[9]);
        acc[10] = fmaf(z2, f.z, acc[10]); acc[11] = fmaf(z2, f.w, acc[11]);
        acc[12] = fmaf(z3, f.x, acc[12]); acc[13] = fmaf(z3, f.y, acc[13]);
        acc[14] = fmaf(z3, f.z, acc[14]); acc[15] = fmaf(z3, f.w, acc[15]);
    }
#pragma unroll
    for (int i = 0; i < 4; i++) {
        float4* d = (float4*)(out + (((size_t)ch * 256) + ht * 64 + rg * 4 + i) * 256 + wt * 64 + wg * 4);
        *d = make_float4(acc[i * 4 + 0], acc[i * 4 + 1], acc[i * 4 + 2], acc[i * 4 + 3]);
    }
}

// ---------------------------------------------------------------------------
extern "C" void kernel_launch(void* const* d_in, const int* in_sizes, int n_in,
                              void* d_out, int out_size) {
    const float* x   = (const float*)d_in[0];
    const float* w1r = (const float*)d_in[1];
    const float* w1i = (const float*)d_in[2];
    const float* w2r = (const float*)d_in[3];
    const float* w2i = (const float*)d_in[4];
    const float* w3r = (const float*)d_in[5];
    const float* w3i = (const float*)d_in[6];
    const float* w4r = (const float*)d_in[7];
    const float* w4i = (const float*)d_in[8];
    float* out = (float*)d_out;

    k_init_mats<<<321, 256>>>();

    // ---- branch x ----
    k_wt<<<8192, 256>>>(w1r, w1i, w2r, w2i);
    k_s1<<<2048, 256>>>(x, 0);
    k_s2<<<512, 256>>>();
    k_s3<<<2048, 512>>>();
    k_s4<<<2048, 256>>>();
    k_s5<<<8192, 256>>>(out);

    // ---- branch x^T ----
    k_wt<<<8192, 256>>>(w3r, w3i, w4r, w4i);
    k_s1<<<2048, 256>>>(x, 1);
    k_s2<<<512, 256>>>();
    k_s3<<<2048, 512>>>();
    k_s4<<<2048, 256>>>();
    k_s5<<<8192, 256>>>(out + (size_t)NCH * 65536);
}

// round 3
// speedup vs baseline: 4.3938x; 1.1308x over previous
#include <cuda_runtime.h>

// ---------------------------------------------------------------------------
// SpectralConv2d (FNO). B=8, C=64, H=W=256, M1=M2=32. Two branches.
// tw[t] = exp(-2*pi*i*t/256): twr=cos, twi=-sin(2 pi t/256).
// Fused pipeline:
//  k_s1s2 (per ch): T chunk (64h x 64c) in smem, accumulate
//         XF[j,k2] = sum_h T[h,k2] * tw[k1(j)h]       (k1(j)= j | 192+j)
//  k_s3:  Y[b,o,j,k2] = sum_i XF[b,i,j,k2]*W[i,o,jw,k2]  (complex, coalesced W)
//  k_s4s5 (per ch,htile): Z[h,k2] = sum_j Y[j,k2]*conj(tw[k1 h]) in smem,
//         out[h,w] = sum_c Z[h,c]*F[c,w]   (halfcomplex irfft fold + 1/65536)
// ---------------------------------------------------------------------------

namespace {
constexpr int NCH = 512;           // B*C
}

__device__ float g_twr[256];
__device__ float g_twi[256];
__device__ float g_E1[256 * 64];             // [w][c], c = 2*k2 + ri
__device__ float g_F [64 * 256];             // [c][w]
__device__ float g_XF[NCH * 64 * 32 * 2];    // [(ch*64+j)*32+k2] complex
__device__ float g_Y [NCH * 64 * 32 * 2];    // same layout

// ---------------- init ------------------------------------------------------
__global__ void k_init_mats() {
    int bid = blockIdx.x;
    int t   = threadIdx.x;
    if (bid < 256) {                      // E1 row w = bid
        if (t < 64) {
            int w = bid, k2 = t >> 1, ri = t & 1;
            int ang = (k2 * w) & 255;
            double s, c;
            sincospi(-2.0 * (double)ang / 256.0, &s, &c);
            g_E1[w * 64 + t] = (float)(ri ? s : c);
        }
    } else if (bid < 320) {               // F row c = bid-256, thread = w
        int cc = bid - 256;
        int w  = t;
        int k2 = cc >> 1, ri = cc & 1;
        int ang = (k2 * w) & 255;
        double s, c;
        sincospi(-2.0 * (double)ang / 256.0, &s, &c);
        const float sc = 1.0f / 65536.0f;
        float v;
        if (k2 == 0) v = ri ? 0.0f : sc;
        else         v = 2.0f * sc * (float)(ri ? s : c);
        g_F[cc * 256 + w] = v;
    } else {
        double s, c;
        sincospi(-2.0 * (double)t / 256.0, &s, &c);
        g_twr[t] = (float)c;
        g_twi[t] = (float)s;
    }
}

// ---------------- fused stage 1+2 -------------------------------------------
// block = channel, 128 threads.
// Phase A (per h-chunk of 64): T[hl][c] = sum_w x * E1,  c = 2k2+ri
//   thread: rows {r2, r2+32} x 16 cols (cg). K=256 in 4 sub-chunks.
// Phase B: XF[j,k2] += sum_hl T[hl][k2] * tw[k1(j)*h]
//   thread: j in {jp, jp+32} x 8 k2-pairs (cg).
__global__ __launch_bounds__(128) void k_s1s2(const float* __restrict__ x, int trans) {
    __shared__ float sbuf[8256];          // xs[64*65] | es[64*64] ; sT aliases base
    __shared__ float str[256], sti[256];
    float* xs = sbuf;
    float* es = sbuf + 4160;
    float* sT = sbuf;                     // 64*68 = 4352 <= 8256

    int t  = threadIdx.x;
    int ch = blockIdx.x;
    const float* xc = x + (size_t)ch * 65536;
    str[t] = g_twr[t]; str[t + 128] = g_twr[t + 128];
    sti[t] = g_twi[t]; sti[t + 128] = g_twi[t + 128];

    int r2 = t >> 2;                      // 0..31
    int cg = t & 3;
    int k1lo = r2;                        // j = jp = r2
    int k1hi = 224 + r2;                  // j = jp+32 -> k1 = 192+j
    float xfr0[8], xfi0[8], xfr1[8], xfi1[8];
#pragma unroll
    for (int p = 0; p < 8; p++) { xfr0[p]=0.f; xfi0[p]=0.f; xfr1[p]=0.f; xfi1[p]=0.f; }

    for (int hc = 0; hc < 4; hc++) {
        float accA[32];
#pragma unroll
        for (int i = 0; i < 32; i++) accA[i] = 0.f;

        for (int kc = 0; kc < 4; kc++) {
            __syncthreads();              // xs/es free (also guards sT from prev B)
            const float4* esrc = (const float4*)(g_E1 + kc * 4096);
            float4* ed = (float4*)es;
#pragma unroll
            for (int q = 0; q < 8; q++) ed[q * 128 + t] = esrc[q * 128 + t];
#pragma unroll
            for (int q = 0; q < 32; q++) {
                int flat = q * 128 + t;
                int i1 = flat >> 6, i2 = flat & 63;
                if (!trans) xs[i2 * 65 + i1] = xc[(hc * 64 + i1) * 256 + kc * 64 + i2];
                else        xs[i1 * 65 + i2] = xc[(kc * 64 + i1) * 256 + hc * 64 + i2];
            }
            __syncthreads();
#pragma unroll 4
            for (int kk = 0; kk < 64; kk++) {
                float a0 = xs[kk * 65 + r2];
                float a1 = xs[kk * 65 + r2 + 32];
                const float4* ek = (const float4*)(es + kk * 64 + cg * 16);
                float4 e0 = ek[0], e1 = ek[1], e2 = ek[2], e3 = ek[3];
                accA[0]  = fmaf(a0, e0.x, accA[0]);  accA[1]  = fmaf(a0, e0.y, accA[1]);
                accA[2]  = fmaf(a0, e0.z, accA[2]);  accA[3]  = fmaf(a0, e0.w, accA[3]);
                accA[4]  = fmaf(a0, e1.x, accA[4]);  accA[5]  = fmaf(a0, e1.y, accA[5]);
                accA[6]  = fmaf(a0, e1.z, accA[6]);  accA[7]  = fmaf(a0, e1.w, accA[7]);
                accA[8]  = fmaf(a0, e2.x, accA[8]);  accA[9]  = fmaf(a0, e2.y, accA[9]);
                accA[10] = fmaf(a0, e2.z, accA[10]); accA[11] = fmaf(a0, e2.w, accA[11]);
                accA[12] = fmaf(a0, e3.x, accA[12]); accA[13] = fmaf(a0, e3.y, accA[13]);
                accA[14] = fmaf(a0, e3.z, accA[14]); accA[15] = fmaf(a0, e3.w, accA[15]);
                accA[16] = fmaf(a1, e0.x, accA[16]); accA[17] = fmaf(a1, e0.y, accA[17]);
                accA[18] = fmaf(a1, e0.z, accA[18]); accA[19] = fmaf(a1, e0.w, accA[19]);
                accA[20] = fmaf(a1, e1.x, accA[20]); accA[21] = fmaf(a1, e1.y, accA[21]);
                accA[22] = fmaf(a1, e1.z, accA[22]); accA[23] = fmaf(a1, e1.w, accA[23]);
                accA[24] = fmaf(a1, e2.x, accA[24]); accA[25] = fmaf(a1, e2.y, accA[25]);
                accA[26] = fmaf(a1, e2.z, accA[26]); accA[27] = fmaf(a1, e2.w, accA[27]);
                accA[28] = fmaf(a1, e3.x, accA[28]); accA[29] = fmaf(a1, e3.y, accA[29]);
                accA[30] = fmaf(a1, e3.z, accA[30]); accA[31] = fmaf(a1, e3.w, accA[31]);
            }
        }
        __syncthreads();                  // done with xs/es -> write sT (aliases)
        {
            float* d0 = sT + r2 * 68 + cg * 16;
            float* d1 = sT + (r2 + 32) * 68 + cg * 16;
#pragma unroll
            for (int i = 0; i < 4; i++) {
                ((float4*)d0)[i] = make_float4(accA[i*4+0], accA[i*4+1], accA[i*4+2], accA[i*4+3]);
                ((float4*)d1)[i] = make_float4(accA[16+i*4+0], accA[16+i*4+1], accA[16+i*4+2], accA[16+i*4+3]);
            }
        }
        __syncthreads();
        // Phase B
#pragma unroll 2
        for (int hh = 0; hh < 64; hh++) {
            int h  = hc * 64 + hh;
            int i0 = (k1lo * h) & 255;
            int i1 = (k1hi * h) & 255;
            float c0 = str[i0], s0 = sti[i0];
            float c1 = str[i1], s1 = sti[i1];
            const float4* Tp = (const float4*)(sT + hh * 68 + cg * 16);
            float4 p0 = Tp[0], p1 = Tp[1], p2 = Tp[2], p3 = Tp[3];
#define CMAC(P, TR, TI) \
            xfr0[P] = fmaf(TR, c0, xfr0[P]); xfr0[P] = fmaf(-(TI), s0, xfr0[P]); \
            xfi0[P] = fmaf(TR, s0, xfi0[P]); xfi0[P] = fmaf( (TI), c0, xfi0[P]); \
            xfr1[P] = fmaf(TR, c1, xfr1[P]); xfr1[P] = fmaf(-(TI), s1, xfr1[P]); \
            xfi1[P] = fmaf(TR, s1, xfi1[P]); xfi1[P] = fmaf( (TI), c1, xfi1[P]);
            CMAC(0, p0.x, p0.y) CMAC(1, p0.z, p0.w)
            CMAC(2, p1.x, p1.y) CMAC(3, p1.z, p1.w)
            CMAC(4, p2.x, p2.y) CMAC(5, p2.z, p2.w)
            CMAC(6, p3.x, p3.y) CMAC(7, p3.z, p3.w)
#undef CMAC
        }
    }
    float2* XF = (float2*)(g_XF + (size_t)ch * 64 * 32 * 2);
#pragma unroll
    for (int p = 0; p < 8; p++) {
        int k2 = cg * 8 + p;
        XF[r2 * 32 + k2]        = make_float2(xfr0[p], xfi0[p]);
        XF[(r2 + 32) * 32 + k2] = make_float2(xfr1[p], xfi1[p]);
    }
}

// ---------------- stage 3: mode mix, direct coalesced weights ---------------
// grid = (j=64) x (o-tile=8); 256 threads = (o within tile = t>>5, k2 = t&31).
__global__ __launch_bounds__(256) void k_s3(const float* __restrict__ wAr,
                                            const float* __restrict__ wAi,
                                            const float* __restrict__ wBr,
                                            const float* __restrict__ wBi) {
    __shared__ float2 sxf[8][16][32];     // 32 KB
    int t  = threadIdx.x;
    int j  = blockIdx.x >> 3;
    int ot = blockIdx.x & 7;
    int o  = ot * 8 + (t >> 5);
    int k2 = t & 31;
    const float* wr; const float* wi; int jw;
    if (j < 32) { wr = wAr; wi = wAi; jw = j; }
    else        { wr = wBr; wi = wBi; jw = j - 32; }
    float yr[8], yi[8];
#pragma unroll
    for (int b = 0; b < 8; b++) { yr[b] = 0.f; yi[b] = 0.f; }
    const float2* XF = (const float2*)g_XF;

    for (int ic = 0; ic < 4; ic++) {
        __syncthreads();
#pragma unroll
        for (int q = 0; q < 16; q++) {
            int flat = q * 256 + t;
            int b  = flat >> 9;
            int ii = (flat >> 5) & 15;
            int kl = flat & 31;
            sxf[b][ii][kl] = XF[((size_t)(b * 64 + ic * 16 + ii) * 64 + j) * 32 + kl];
        }
        __syncthreads();
#pragma unroll 4
        for (int ii = 0; ii < 16; ii++) {
            int i = ic * 16 + ii;
            size_t widx = (size_t)(i * 64 + o) * 1024 + jw * 32 + k2;
            float wre = wr[widx];
            float wim = wi[widx];
#pragma unroll
            for (int b = 0; b < 8; b++) {
                float2 xv = sxf[b][ii][k2];
                yr[b] = fmaf(xv.x, wre, yr[b]); yr[b] = fmaf(-xv.y, wim, yr[b]);
                yi[b] = fmaf(xv.x, wim, yi[b]); yi[b] = fmaf( xv.y, wre, yi[b]);
            }
        }
    }
    float2* Y = (float2*)g_Y;
#pragma unroll
    for (int b = 0; b < 8; b++)
        Y[((size_t)(b * 64 + o) * 64 + j) * 32 + k2] = make_float2(yr[b], yi[b]);
}

// ---------------- fused stage 4+5 -------------------------------------------
// block = (ch, h-tile of 64), 128 threads.
// Phase A: Z[h][c] = sum_j Y[j,k2]*conj(tw[k1 h]); thread: h in {hp,hp+32} x 8 pairs.
// Phase B: out[64h x 64w tiles] = Z(64x64) . F(64x64), thread 4h x 8w.
__global__ __launch_bounds__(128) void k_s4s5(float* __restrict__ out) {
    __shared__ float zs[64 * 68];         // Z transposed: [c][h]
    __shared__ float reg2[4096];          // sY then fs
    __shared__ float str[256], sti[256];
    int t  = threadIdx.x;
    int ch = blockIdx.x >> 2;
    int ht = blockIdx.x & 3;
    int h0 = ht * 64;
    str[t] = g_twr[t]; str[t + 128] = g_twr[t + 128];
    sti[t] = g_twi[t]; sti[t + 128] = g_twi[t + 128];

    const float4* ys = (const float4*)(g_Y + (size_t)ch * 4096);
    float4* yd = (float4*)reg2;
#pragma unroll
    for (int q = 0; q < 8; q++) yd[q * 128 + t] = ys[q * 128 + t];
    __syncthreads();

    int hp = t >> 2;                      // 0..31
    int cg = t & 3;
    float zr0[8], zi0[8], zr1[8], zi1[8];
#pragma unroll
    for (int p = 0; p < 8; p++) { zr0[p]=0.f; zi0[p]=0.f; zr1[p]=0.f; zi1[p]=0.f; }

#pragma unroll 2
    for (int j = 0; j < 64; j++) {
        int k1 = (j < 32) ? j : (192 + j);
        int ia = (k1 * (h0 + hp)) & 255;
        int ib = (ia + k1 * 32) & 255;
        float ca = str[ia], sa = sti[ia];
        float cb = str[ib], sb = sti[ib];
        const float4* Yp = (const float4*)(reg2 + j * 64 + cg * 16);
        float4 p0 = Yp[0], p1 = Yp[1], p2 = Yp[2], p3 = Yp[3];
#define IMAC(P, YR, YI) \
        zr0[P] = fmaf(YR, ca, zr0[P]); zr0[P] = fmaf(YI, sa, zr0[P]); \
        zi0[P] = fmaf(YI, ca, zi0[P]); zi0[P] = fmaf(-(YR), sa, zi0[P]); \
        zr1[P] = fmaf(YR, cb, zr1[P]); zr1[P] = fmaf(YI, sb, zr1[P]); \
        zi1[P] = fmaf(YI, cb, zi1[P]); zi1[P] = fmaf(-(YR), sb, zi1[P]);
        IMAC(0, p0.x, p0.y) IMAC(1, p0.z, p0.w)
        IMAC(2, p1.x, p1.y) IMAC(3, p1.z, p1.w)
        IMAC(4, p2.x, p2.y) IMAC(5, p2.z, p2.w)
        IMAC(6, p3.x, p3.y) IMAC(7, p3.z, p3.w)
#undef IMAC
    }
    __syncthreads();
#pragma unroll
    for (int p = 0; p < 8; p++) {
        int c2 = cg * 8 + p;
        zs[(2 * c2)     * 68 + hp]      = zr0[p];
        zs[(2 * c2 + 1) * 68 + hp]      = zi0[p];
        zs[(2 * c2)     * 68 + hp + 32] = zr1[p];
        zs[(2 * c2 + 1) * 68 + hp + 32] = zi1[p];
    }

    int hg = t >> 3;                      // 0..15 -> rows 4hg..4hg+3
    int wg = t & 7;                       // cols wg*8..+7
    const float4* Fs = (const float4*)g_F;
    for (int wt = 0; wt < 4; wt++) {
        __syncthreads();                  // reg2 free
        float4* fd = (float4*)reg2;
#pragma unroll
        for (int q = 0; q < 8; q++) {
            int flat = q * 128 + t;
            int c = flat >> 4, u = flat & 15;
            fd[c * 16 + u] = Fs[c * 64 + wt * 16 + u];
        }
        __syncthreads();
        float acc[32];
#pragma unroll
        for (int i = 0; i < 32; i++) acc[i] = 0.f;
#pragma unroll 4
        for (int c = 0; c < 64; c++) {
            float4 a  = *(const float4*)(zs + c * 68 + hg * 4);
            float4 f0 = *(const float4*)(reg2 + c * 64 + wg * 8);
            float4 f1 = *(const float4*)(reg2 + c * 64 + wg * 8 + 4);
#define ROW(R, AV) \
            acc[R*8+0] = fmaf(AV, f0.x, acc[R*8+0]); acc[R*8+1] = fmaf(AV, f0.y, acc[R*8+1]); \
            acc[R*8+2] = fmaf(AV, f0.z, acc[R*8+2]); acc[R*8+3] = fmaf(AV, f0.w, acc[R*8+3]); \
            acc[R*8+4] = fmaf(AV, f1.x, acc[R*8+4]); acc[R*8+5] = fmaf(AV, f1.y, acc[R*8+5]); \
            acc[R*8+6] = fmaf(AV, f1.z, acc[R*8+6]); acc[R*8+7] = fmaf(AV, f1.w, acc[R*8+7]);
            ROW(0, a.x) ROW(1, a.y) ROW(2, a.z) ROW(3, a.w)
#undef ROW
        }
#pragma unroll
        for (int r = 0; r < 4; r++) {
            float* dp = out + ((size_t)ch * 256 + h0 + hg * 4 + r) * 256 + wt * 64 + wg * 8;
            ((float4*)dp)[0] = make_float4(acc[r*8+0], acc[r*8+1], acc[r*8+2], acc[r*8+3]);
            ((float4*)dp)[1] = make_float4(acc[r*8+4], acc[r*8+5], acc[r*8+6], acc[r*8+7]);
        }
    }
}

// ---------------------------------------------------------------------------
extern "C" void kernel_launch(void* const* d_in, const int* in_sizes, int n_in,
                              void* d_out, int out_size) {
    const float* x   = (const float*)d_in[0];
    const float* w1r = (const float*)d_in[1];
    const float* w1i = (const float*)d_in[2];
    const float* w2r = (const float*)d_in[3];
    const float* w2i = (const float*)d_in[4];
    const float* w3r = (const float*)d_in[5];
    const float* w3i = (const float*)d_in[6];
    const float* w4r = (const float*)d_in[7];
    const float* w4i = (const float*)d_in[8];
    float* out = (float*)d_out;

    k_init_mats<<<321, 256>>>();

    // ---- branch x ----
    k_s1s2<<<512, 128>>>(x, 0);
    k_s3<<<512, 256>>>(w1r, w1i, w2r, w2i);
    k_s4s5<<<2048, 128>>>(out);

    // ---- branch x^T ----
    k_s1s2<<<512, 128>>>(x, 1);
    k_s3<<<512, 256>>>(w3r, w3i, w4r, w4i);
    k_s4s5<<<2048, 128>>>(out + (size_t)NCH * 65536);
}

// round 4
// speedup vs baseline: 7.9091x; 1.8001x over previous
#include <cuda_runtime.h>

// ---------------------------------------------------------------------------
// SpectralConv2d (FNO). B=8, C=64, H=W=256, M1=M2=32. Two branches.
// v4: cosine/sine symmetry folding (S1, S5 K halved) + packed fma.rn.f32x2.
// ---------------------------------------------------------------------------

namespace {
constexpr int NCH = 512;           // B*C
}

typedef unsigned long long ull;

__device__ __forceinline__ ull pk2(float lo, float hi) {
    ull r; asm("mov.b64 %0, {%1,%2};" : "=l"(r) : "f"(lo), "f"(hi)); return r;
}
__device__ __forceinline__ ull ffma2(ull a, ull b, ull c) {
    ull d; asm("fma.rn.f32x2 %0, %1, %2, %3;" : "=l"(d) : "l"(a), "l"(b), "l"(c)); return d;
}
__device__ __forceinline__ ull add2(ull a, ull b) {
    ull d; asm("add.rn.f32x2 %0, %1, %2;" : "=l"(d) : "l"(a), "l"(b)); return d;
}
__device__ __forceinline__ float2 upk(ull v) {
    float2 r; asm("mov.b64 {%0,%1}, %2;" : "=f"(r.x), "=f"(r.y) : "l"(v)); return r;
}

__device__ float g_twr[256];
__device__ float g_twi[256];
__device__ float g_Cc[128 * 32];             // cos(2pi k2 w'/256), [w'][k2]
__device__ float g_Cs[128 * 32];             // -sin(...)           [w'][k2]
__device__ float g_Fc[32 * 128];             // sc*(k2?2cos:1)      [k2][w']
__device__ float g_Fs[32 * 128];             // k2? -2sc*sin : 0    [k2][w']
__device__ float g_XF[NCH * 64 * 32 * 2];    // [(ch*64+j)*32+k2] complex
__device__ float g_Y [NCH * 64 * 32 * 2];    // same layout

// ---------------- init ------------------------------------------------------
__global__ void k_init() {
    int idx = blockIdx.x * 256 + threadIdx.x;
    const float sc = 1.0f / 65536.0f;
    if (idx < 256) {
        double s, c;
        sincospi(-2.0 * (double)idx / 256.0, &s, &c);
        g_twr[idx] = (float)c;
        g_twi[idx] = (float)s;
    } else if (idx < 256 + 4096) {
        int j = idx - 256;
        int wp = j >> 5, k2 = j & 31;
        int ang = (k2 * wp) & 255;
        double s, c;
        sincospi(-2.0 * (double)ang / 256.0, &s, &c);
        g_Cc[wp * 32 + k2] = (float)c;       // cos(theta)
        g_Cs[wp * 32 + k2] = (float)s;       // -sin(theta)
    } else if (idx < 256 + 8192) {
        int j = idx - 4352;
        int k2 = j >> 7, wp = j & 127;
        int ang = (k2 * wp) & 255;
        double s, c;
        sincospi(-2.0 * (double)ang / 256.0, &s, &c);
        g_Fc[k2 * 128 + wp] = (k2 == 0) ? sc : 2.0f * sc * (float)c;
        g_Fs[k2 * 128 + wp] = (k2 == 0) ? 0.0f : 2.0f * sc * (float)s;
    }
}

// ---------------- fused stage 1+2 -------------------------------------------
// block = channel, 128 threads.
// Phase A (folded, FFMA2): Tr[k2] = sum_{w'<128} xe*cos + x128*(-1)^k2,
//                          Ti[k2] = sum xo*(-sin)   -> sT interleaved [h][2k2+ri]
// Phase B (unchanged): XF[j,k2] += sum_h T[h,k2]*tw[k1(j)h]
__global__ __launch_bounds__(128) void k_s1s2(const float* __restrict__ x, int trans) {
    __shared__ float buf[6208];  // [xe 2080 | xo 2080 | Cc 1024 | Cs 1024]; sT aliases [0..4351]
    __shared__ float str[256], sti[256];
    __shared__ float sx128[64];
    float* xe  = buf;
    float* xo  = buf + 2080;
    float* sCc = buf + 4160;
    float* sCs = buf + 5184;
    float* sT  = buf;            // 64*68 = 4352, alias over xe+xo

    int t  = threadIdx.x;
    int ch = blockIdx.x;
    const float* xc = x + (size_t)ch * 65536;
    str[t] = g_twr[t]; str[t + 128] = g_twr[t + 128];
    sti[t] = g_twi[t]; sti[t + 128] = g_twi[t + 128];

    int r2 = t >> 2;                      // 0..31
    int cg = t & 3;
    int k1lo = r2;
    int k1hi = 224 + r2;
    float xfr0[8], xfi0[8], xfr1[8], xfi1[8];
#pragma unroll
    for (int p = 0; p < 8; p++) { xfr0[p]=0.f; xfi0[p]=0.f; xfr1[p]=0.f; xfi1[p]=0.f; }

    for (int hc = 0; hc < 4; hc++) {
        ull Tr0[4], Ti0[4], Tr1[4], Ti1[4];
#pragma unroll
        for (int q = 0; q < 4; q++) { Tr0[q]=0ull; Ti0[q]=0ull; Tr1[q]=0ull; Ti1[q]=0ull; }

        for (int kc = 0; kc < 4; kc++) {
            __syncthreads();              // prev compute / prev Phase-B sT reads done
            // stage C chunk: rows kc*32..kc*32+31 of [128][32]
            {
                const float4* cc4 = (const float4*)(g_Cc + kc * 1024);
                const float4* cs4 = (const float4*)(g_Cs + kc * 1024);
                float4* d1 = (float4*)sCc;
                float4* d2 = (float4*)sCs;
#pragma unroll
                for (int q = 0; q < 2; q++) {
                    d1[q * 128 + t] = cc4[q * 128 + t];
                    d2[q * 128 + t] = cs4[q * 128 + t];
                }
            }
            // fill xe/xo (fold), w' in [kc*32, kc*32+32), rows hc*64..+63
#pragma unroll
            for (int q = 0; q < 16; q++) {
                int flat = q * 128 + t;
                int wl, row;
                if (!trans) { wl = flat & 31; row = flat >> 5; }
                else        { row = flat & 63; wl = flat >> 6; }
                int wp = kc * 32 + wl;
                float xv, xm;
                if (!trans) {
                    xv = xc[(hc * 64 + row) * 256 + wp];
                    xm = (wp == 0) ? 0.f : xc[(hc * 64 + row) * 256 + 256 - wp];
                } else {
                    xv = xc[wp * 256 + hc * 64 + row];
                    xm = (wp == 0) ? 0.f : xc[(256 - wp) * 256 + hc * 64 + row];
                }
                xe[wl * 65 + row] = (wp == 0) ? xv : xv + xm;
                xo[wl * 65 + row] = (wp == 0) ? 0.f : xv - xm;
                if (wp == 0)
                    sx128[row] = (!trans) ? xc[(hc * 64 + row) * 256 + 128]
                                          : xc[128 * 256 + hc * 64 + row];
            }
            __syncthreads();
#pragma unroll 4
            for (int kk = 0; kk < 32; kk++) {
                float a0e = xe[kk * 65 + r2];
                float a1e = xe[kk * 65 + r2 + 32];
                float a0o = xo[kk * 65 + r2];
                float a1o = xo[kk * 65 + r2 + 32];
                ull pa0e = pk2(a0e, a0e), pa1e = pk2(a1e, a1e);
                ull pa0o = pk2(a0o, a0o), pa1o = pk2(a1o, a1o);
                const float* cp = sCc + kk * 32 + cg * 8;
                const float* sp = sCs + kk * 32 + cg * 8;
                ulonglong2 c0 = *(const ulonglong2*)cp;
                ulonglong2 c1 = *(const ulonglong2*)(cp + 4);
                ulonglong2 s0 = *(const ulonglong2*)sp;
                ulonglong2 s1 = *(const ulonglong2*)(sp + 4);
                Tr0[0] = ffma2(pa0e, c0.x, Tr0[0]); Tr0[1] = ffma2(pa0e, c0.y, Tr0[1]);
                Tr0[2] = ffma2(pa0e, c1.x, Tr0[2]); Tr0[3] = ffma2(pa0e, c1.y, Tr0[3]);
                Tr1[0] = ffma2(pa1e, c0.x, Tr1[0]); Tr1[1] = ffma2(pa1e, c0.y, Tr1[1]);
                Tr1[2] = ffma2(pa1e, c1.x, Tr1[2]); Tr1[3] = ffma2(pa1e, c1.y, Tr1[3]);
                Ti0[0] = ffma2(pa0o, s0.x, Ti0[0]); Ti0[1] = ffma2(pa0o, s0.y, Ti0[1]);
                Ti0[2] = ffma2(pa0o, s1.x, Ti0[2]); Ti0[3] = ffma2(pa0o, s1.y, Ti0[3]);
                Ti1[0] = ffma2(pa1o, s0.x, Ti1[0]); Ti1[1] = ffma2(pa1o, s0.y, Ti1[1]);
                Ti1[2] = ffma2(pa1o, s1.x, Ti1[2]); Ti1[3] = ffma2(pa1o, s1.y, Ti1[3]);
            }
        }
        // x[128] parity term: Tr[k2] += x128 * (-1)^k2 (pairs are (even,odd))
        {
            const ull PM = pk2(1.f, -1.f);
            ull px0 = pk2(sx128[r2], sx128[r2]);
            ull px1 = pk2(sx128[r2 + 32], sx128[r2 + 32]);
#pragma unroll
            for (int q = 0; q < 4; q++) {
                Tr0[q] = ffma2(px0, PM, Tr0[q]);
                Tr1[q] = ffma2(px1, PM, Tr1[q]);
            }
        }
        __syncthreads();                  // compute reads done; overwrite alias with sT
#pragma unroll
        for (int q = 0; q < 4; q++) {
            int k2a = cg * 8 + 2 * q;
            float2 tr0 = upk(Tr0[q]), ti0 = upk(Ti0[q]);
            float2 tr1 = upk(Tr1[q]), ti1 = upk(Ti1[q]);
            sT[r2 * 68 + 2 * k2a]           = tr0.x;
            sT[r2 * 68 + 2 * k2a + 1]       = ti0.x;
            sT[r2 * 68 + 2 * k2a + 2]       = tr0.y;
            sT[r2 * 68 + 2 * k2a + 3]       = ti0.y;
            sT[(r2 + 32) * 68 + 2 * k2a]     = tr1.x;
            sT[(r2 + 32) * 68 + 2 * k2a + 1] = ti1.x;
            sT[(r2 + 32) * 68 + 2 * k2a + 2] = tr1.y;
            sT[(r2 + 32) * 68 + 2 * k2a + 3] = ti1.y;
        }
        __syncthreads();
        // Phase B (unchanged)
#pragma unroll 2
        for (int hh = 0; hh < 64; hh++) {
            int h  = hc * 64 + hh;
            int i0 = (k1lo * h) & 255;
            int i1 = (k1hi * h) & 255;
            float c0 = str[i0], s0 = sti[i0];
            float c1 = str[i1], s1 = sti[i1];
            const float4* Tp = (const float4*)(sT + hh * 68 + cg * 16);
            float4 p0 = Tp[0], p1 = Tp[1], p2 = Tp[2], p3 = Tp[3];
#define CMAC(P, TR, TI) \
            xfr0[P] = fmaf(TR, c0, xfr0[P]); xfr0[P] = fmaf(-(TI), s0, xfr0[P]); \
            xfi0[P] = fmaf(TR, s0, xfi0[P]); xfi0[P] = fmaf( (TI), c0, xfi0[P]); \
            xfr1[P] = fmaf(TR, c1, xfr1[P]); xfr1[P] = fmaf(-(TI), s1, xfr1[P]); \
            xfi1[P] = fmaf(TR, s1, xfi1[P]); xfi1[P] = fmaf( (TI), c1, xfi1[P]);
            CMAC(0, p0.x, p0.y) CMAC(1, p0.z, p0.w)
            CMAC(2, p1.x, p1.y) CMAC(3, p1.z, p1.w)
            CMAC(4, p2.x, p2.y) CMAC(5, p2.z, p2.w)
            CMAC(6, p3.x, p3.y) CMAC(7, p3.z, p3.w)
#undef CMAC
        }
    }
    float2* XF = (float2*)(g_XF + (size_t)ch * 64 * 32 * 2);
#pragma unroll
    for (int p = 0; p < 8; p++) {
        int k2 = cg * 8 + p;
        XF[r2 * 32 + k2]        = make_float2(xfr0[p], xfi0[p]);
        XF[(r2 + 32) * 32 + k2] = make_float2(xfr1[p], xfi1[p]);
    }
}

// ---------------- stage 3: mode mix (unchanged) -----------------------------
__global__ __launch_bounds__(256) void k_s3(const float* __restrict__ wAr,
                                            const float* __restrict__ wAi,
                                            const float* __restrict__ wBr,
                                            const float* __restrict__ wBi) {
    __shared__ float2 sxf[8][16][32];
    int t  = threadIdx.x;
    int j  = blockIdx.x >> 3;
    int ot = blockIdx.x & 7;
    int o  = ot * 8 + (t >> 5);
    int k2 = t & 31;
    const float* wr; const float* wi; int jw;
    if (j < 32) { wr = wAr; wi = wAi; jw = j; }
    else        { wr = wBr; wi = wBi; jw = j - 32; }
    float yr[8], yi[8];
#pragma unroll
    for (int b = 0; b < 8; b++) { yr[b] = 0.f; yi[b] = 0.f; }
    const float2* XF = (const float2*)g_XF;

    for (int ic = 0; ic < 4; ic++) {
        __syncthreads();
#pragma unroll
        for (int q = 0; q < 16; q++) {
            int flat = q * 256 + t;
            int b  = flat >> 9;
            int ii = (flat >> 5) & 15;
            int kl = flat & 31;
            sxf[b][ii][kl] = XF[((size_t)(b * 64 + ic * 16 + ii) * 64 + j) * 32 + kl];
        }
        __syncthreads();
#pragma unroll 4
        for (int ii = 0; ii < 16; ii++) {
            int i = ic * 16 + ii;
            size_t widx = (size_t)(i * 64 + o) * 1024 + jw * 32 + k2;
            float wre = wr[widx];
            float wim = wi[widx];
#pragma unroll
            for (int b = 0; b < 8; b++) {
                float2 xv = sxf[b][ii][k2];
                yr[b] = fmaf(xv.x, wre, yr[b]); yr[b] = fmaf(-xv.y, wim, yr[b]);
                yi[b] = fmaf(xv.x, wim, yi[b]); yi[b] = fmaf( xv.y, wre, yi[b]);
            }
        }
    }
    float2* Y = (float2*)g_Y;
#pragma unroll
    for (int b = 0; b < 8; b++)
        Y[((size_t)(b * 64 + o) * 64 + j) * 32 + k2] = make_float2(yr[b], yi[b]);
}

// ---------------- fused stage 4+5 -------------------------------------------
// Phase A (unchanged): Z into smem planes zs[2k2][h] / zs[2k2+1][h].
// Phase B (folded, FFMA2): P=Zr.Fc, Q=Zi.Fs over w'=0..127;
//   out[w'] = P+Q, out[256-w'] = P-Q, out[128] parity column.
__global__ __launch_bounds__(128) void k_s4s5(float* __restrict__ out) {
    __shared__ float zs[64 * 68];
    __shared__ float reg2[4096];
    __shared__ float str[256], sti[256];
    int t  = threadIdx.x;
    int ch = blockIdx.x >> 2;
    int ht = blockIdx.x & 3;
    int h0 = ht * 64;
    str[t] = g_twr[t]; str[t + 128] = g_twr[t + 128];
    sti[t] = g_twi[t]; sti[t + 128] = g_twi[t + 128];

    const float4* ys = (const float4*)(g_Y + (size_t)ch * 4096);
    float4* yd = (float4*)reg2;
#pragma unroll
    for (int q = 0; q < 8; q++) yd[q * 128 + t] = ys[q * 128 + t];
    __syncthreads();

    int hp = t >> 2;
    int cg = t & 3;
    float zr0[8], zi0[8], zr1[8], zi1[8];
#pragma unroll
    for (int p = 0; p < 8; p++) { zr0[p]=0.f; zi0[p]=0.f; zr1[p]=0.f; zi1[p]=0.f; }

#pragma unroll 2
    for (int j = 0; j < 64; j++) {
        int k1 = (j < 32) ? j : (192 + j);
        int ia = (k1 * (h0 + hp)) & 255;
        int ib = (ia + k1 * 32) & 255;
        float ca = str[ia], sa = sti[ia];
        float cb = str[ib], sb = sti[ib];
        const float4* Yp = (const float4*)(reg2 + j * 64 + cg * 16);
        float4 p0 = Yp[0], p1 = Yp[1], p2 = Yp[2], p3 = Yp[3];
#define IMAC(P, YR, YI) \
        zr0[P] = fmaf(YR, ca, zr0[P]); zr0[P] = fmaf(YI, sa, zr0[P]); \
        zi0[P] = fmaf(YI, ca, zi0[P]); zi0[P] = fmaf(-(YR), sa, zi0[P]); \
        zr1[P] = fmaf(YR, cb, zr1[P]); zr1[P] = fmaf(YI, sb, zr1[P]); \
        zi1[P] = fmaf(YI, cb, zi1[P]); zi1[P] = fmaf(-(YR), sb, zi1[P]);
        IMAC(0, p0.x, p0.y) IMAC(1, p0.z, p0.w)
        IMAC(2, p1.x, p1.y) IMAC(3, p1.z, p1.w)
        IMAC(4, p2.x, p2.y) IMAC(5, p2.z, p2.w)
        IMAC(6, p3.x, p3.y) IMAC(7, p3.z, p3.w)
#undef IMAC
    }
    __syncthreads();
#pragma unroll
    for (int p = 0; p < 8; p++) {
        int c2 = cg * 8 + p;
        zs[(2 * c2)     * 68 + hp]      = zr0[p];
        zs[(2 * c2 + 1) * 68 + hp]      = zi0[p];
        zs[(2 * c2)     * 68 + hp + 32] = zr1[p];
        zs[(2 * c2 + 1) * 68 + hp + 32] = zi1[p];
    }

    // -------- Phase B: folded inverse-w --------
    int hg = t >> 3;                      // 0..15 -> local rows hg*4..+3
    int wg = t & 7;                       // w' cols wg*8..+7 (within 64-chunk)
    const float4* FcG = (const float4*)g_Fc;
    const float4* FsG = (const float4*)g_Fs;
    const ull M1 = pk2(-1.f, -1.f);
    for (int wt = 0; wt < 2; wt++) {
        __syncthreads();
        float4* fd = (float4*)reg2;
#pragma unroll
        for (int q = 0; q < 4; q++) {
            int flat = q * 128 + t;
            int k2 = flat >> 4, u = flat & 15;
            fd[k2 * 16 + u]       = FcG[k2 * 32 + wt * 16 + u];
            fd[512 + k2 * 16 + u] = FsG[k2 * 32 + wt * 16 + u];
        }
        __syncthreads();
        ull P[16], Q[16];
#pragma unroll
        for (int q = 0; q < 16; q++) { P[q] = 0ull; Q[q] = 0ull; }
#pragma unroll 4
        for (int k2 = 0; k2 < 32; k2++) {
            float4 a = *(const float4*)(zs + (2 * k2) * 68 + hg * 4);
            float4 b = *(const float4*)(zs + (2 * k2 + 1) * 68 + hg * 4);
            const float* fp = reg2 + k2 * 64 + wg * 8;
            ulonglong2 f0 = *(const ulonglong2*)fp;
            ulonglong2 f1 = *(const ulonglong2*)(fp + 4);
            ulonglong2 g0 = *(const ulonglong2*)(fp + 2048);
            ulonglong2 g1 = *(const ulonglong2*)(fp + 2052);
            ull pr, pi;
#define BROW(R, AV, BV) \
            pr = pk2(AV, AV); pi = pk2(BV, BV); \
            P[R*4+0] = ffma2(pr, f0.x, P[R*4+0]); P[R*4+1] = ffma2(pr, f0.y, P[R*4+1]); \
            P[R*4+2] = ffma2(pr, f1.x, P[R*4+2]); P[R*4+3] = ffma2(pr, f1.y, P[R*4+3]); \
            Q[R*4+0] = ffma2(pi, g0.x, Q[R*4+0]); Q[R*4+1] = ffma2(pi, g0.y, Q[R*4+1]); \
            Q[R*4+2] = ffma2(pi, g1.x, Q[R*4+2]); Q[R*4+3] = ffma2(pi, g1.y, Q[R*4+3]);
            BROW(0, a.x, b.x) BROW(1, a.y, b.y) BROW(2, a.z, b.z) BROW(3, a.w, b.w)
#undef BROW
        }
#pragma unroll
        for (int r = 0; r < 4; r++) {
            int hloc = hg * 4 + r;
            float* orow = out + ((size_t)ch * 256 + h0 + hloc) * 256;
            int wbase = wt * 64 + wg * 8;
            float fw[8], bw[8];
#pragma unroll
            for (int q = 0; q < 4; q++) {
                ull A  = add2(P[r * 4 + q], Q[r * 4 + q]);
                ull Bv = ffma2(Q[r * 4 + q], M1, P[r * 4 + q]);
                float2 fa = upk(A), fb = upk(Bv);
                fw[2 * q] = fa.x; fw[2 * q + 1] = fa.y;
                bw[2 * q] = fb.x; bw[2 * q + 1] = fb.y;
            }
            ((float4*)(orow + wbase))[0] = make_float4(fw[0], fw[1], fw[2], fw[3]);
            ((float4*)(orow + wbase))[1] = make_float4(fw[4], fw[5], fw[6], fw[7]);
#pragma unroll
            for (int i = 0; i < 8; i++) {
                int wv = wbase + i;
                if (wv) orow[256 - wv] = bw[i];
            }
        }
    }
    // w = 128 column: out[h][128] = sc * (Zr[0] + sum_{k2>=1} 2*(-1)^k2 Zr[k2])
    if (t < 64) {
        float s = zs[t];
#pragma unroll
        for (int k2 = 1; k2 < 32; k2++)
            s += ((k2 & 1) ? -2.f : 2.f) * zs[2 * k2 * 68 + t];
        out[((size_t)ch * 256 + h0 + t) * 256 + 128] = s * (1.f / 65536.f);
    }
}

// ---------------------------------------------------------------------------
extern "C" void kernel_launch(void* const* d_in, const int* in_sizes, int n_in,
                              void* d_out, int out_size) {
    const float* x   = (const float*)d_in[0];
    const float* w1r = (const float*)d_in[1];
    const float* w1i = (const float*)d_in[2];
    const float* w2r = (const float*)d_in[3];
    const float* w2i = (const float*)d_in[4];
    const float* w3r = (const float*)d_in[5];
    const float* w3i = (const float*)d_in[6];
    const float* w4r = (const float*)d_in[7];
    const float* w4i = (const float*)d_in[8];
    float* out = (float*)d_out;

    k_init<<<34, 256>>>();

    // ---- branch x ----
    k_s1s2<<<512, 128>>>(x, 0);
    k_s3<<<512, 256>>>(w1r, w1i, w2r, w2i);
    k_s4s5<<<2048, 128>>>(out);

    // ---- branch x^T ----
    k_s1s2<<<512, 128>>>(x, 1);
    k_s3<<<512, 256>>>(w3r, w3i, w4r, w4i);
    k_s4s5<<<2048, 128>>>(out + (size_t)NCH * 65536);
}

// round 5
// speedup vs baseline: 9.3761x; 1.1855x over previous
#include <cuda_runtime.h>

// ---------------------------------------------------------------------------
// SpectralConv2d (FNO). B=8, C=64, H=W=256, M1=M2=32. Two branches.
// v5: j-parity fold in inverse h-DFT (half FLOPs+LDS), FFMA2 everywhere.
// ---------------------------------------------------------------------------

namespace {
constexpr int NCH = 512;           // B*C
}

typedef unsigned long long ull;

__device__ __forceinline__ ull pk2(float lo, float hi) {
    ull r; asm("mov.b64 %0, {%1,%2};" : "=l"(r) : "f"(lo), "f"(hi)); return r;
}
__device__ __forceinline__ ull ffma2(ull a, ull b, ull c) {
    ull d; asm("fma.rn.f32x2 %0, %1, %2, %3;" : "=l"(d) : "l"(a), "l"(b), "l"(c)); return d;
}
__device__ __forceinline__ ull add2(ull a, ull b) {
    ull d; asm("add.rn.f32x2 %0, %1, %2;" : "=l"(d) : "l"(a), "l"(b)); return d;
}
__device__ __forceinline__ float2 upk(ull v) {
    float2 r; asm("mov.b64 {%0,%1}, %2;" : "=f"(r.x), "=f"(r.y) : "l"(v)); return r;
}

__device__ float g_twr[256];
__device__ float g_twi[256];
__device__ float g_Cc[128 * 32];             // cos(2pi k2 w'/256) [w'][k2]
__device__ float g_Cs[128 * 32];             // -sin               [w'][k2]
__device__ float g_Fc[32 * 128];             // sc*(k2?2cos:1)     [k2][w']
__device__ float g_Fs[32 * 128];             // k2? -2sc*sin : 0   [k2][w']
__device__ float g_XF[NCH * 64 * 32 * 2];
__device__ float g_Y [NCH * 64 * 32 * 2];

// ---------------- init ------------------------------------------------------
__global__ void k_init() {
    int idx = blockIdx.x * 256 + threadIdx.x;
    const float sc = 1.0f / 65536.0f;
    if (idx < 256) {
        double s, c;
        sincospi(-2.0 * (double)idx / 256.0, &s, &c);
        g_twr[idx] = (float)c;
        g_twi[idx] = (float)s;
    } else if (idx < 256 + 4096) {
        int j = idx - 256;
        int wp = j >> 5, k2 = j & 31;
        int ang = (k2 * wp) & 255;
        double s, c;
        sincospi(-2.0 * (double)ang / 256.0, &s, &c);
        g_Cc[wp * 32 + k2] = (float)c;
        g_Cs[wp * 32 + k2] = (float)s;
    } else if (idx < 256 + 8192) {
        int j = idx - 4352;
        int k2 = j >> 7, wp = j & 127;
        int ang = (k2 * wp) & 255;
        double s, c;
        sincospi(-2.0 * (double)ang / 256.0, &s, &c);
        g_Fc[k2 * 128 + wp] = (k2 == 0) ? sc : 2.0f * sc * (float)c;
        g_Fs[k2 * 128 + wp] = (k2 == 0) ? 0.0f : 2.0f * sc * (float)s;
    }
}

// ---------------- fused stage 1+2 -------------------------------------------
__global__ __launch_bounds__(128) void k_s1s2(const float* __restrict__ x, int trans) {
    __shared__ ull bufu[3104];            // A-buffers / Tr,Ti planes (aliased)
    __shared__ float str[256], sti[256];
    __shared__ float sx128[64];
    float* buf = (float*)bufu;
    float* xe  = buf;
    float* xo  = buf + 2080;
    float* sCc = buf + 4160;
    float* sCs = buf + 5184;
    ull* sTr = bufu;                      // [64 h][18 ull] (16 used, pad 2)
    ull* sTi = bufu + 1152;

    int t  = threadIdx.x;
    int ch = blockIdx.x;
    const float* xc = x + (size_t)ch * 65536;
    str[t] = g_twr[t]; str[t + 128] = g_twr[t + 128];
    sti[t] = g_twi[t]; sti[t + 128] = g_twi[t + 128];

    int r2 = t >> 2;                      // 0..31
    int cg = t & 3;
    int k1lo = r2;
    int k1hi = 224 + r2;
    ull xfr0p[4], xfi0p[4], xfr1p[4], xfi1p[4];
#pragma unroll
    for (int q = 0; q < 4; q++) { xfr0p[q]=0ull; xfi0p[q]=0ull; xfr1p[q]=0ull; xfi1p[q]=0ull; }

    for (int hc = 0; hc < 4; hc++) {
        ull Tr0[4], Ti0[4], Tr1[4], Ti1[4];
#pragma unroll
        for (int q = 0; q < 4; q++) { Tr0[q]=0ull; Ti0[q]=0ull; Tr1[q]=0ull; Ti1[q]=0ull; }

        for (int kc = 0; kc < 4; kc++) {
            __syncthreads();
            {
                const float4* cc4 = (const float4*)(g_Cc + kc * 1024);
                const float4* cs4 = (const float4*)(g_Cs + kc * 1024);
                float4* d1 = (float4*)sCc;
                float4* d2 = (float4*)sCs;
#pragma unroll
                for (int q = 0; q < 2; q++) {
                    d1[q * 128 + t] = cc4[q * 128 + t];
                    d2[q * 128 + t] = cs4[q * 128 + t];
                }
            }
#pragma unroll
            for (int q = 0; q < 16; q++) {
                int flat = q * 128 + t;
                int wl, row;
                if (!trans) { wl = flat & 31; row = flat >> 5; }
                else        { row = flat & 63; wl = flat >> 6; }
                int wp = kc * 32 + wl;
                float xv, xm;
                if (!trans) {
                    xv = xc[(hc * 64 + row) * 256 + wp];
                    xm = (wp == 0) ? 0.f : xc[(hc * 64 + row) * 256 + 256 - wp];
                } else {
                    xv = xc[wp * 256 + hc * 64 + row];
                    xm = (wp == 0) ? 0.f : xc[(256 - wp) * 256 + hc * 64 + row];
                }
                xe[wl * 65 + row] = (wp == 0) ? xv : xv + xm;
                xo[wl * 65 + row] = (wp == 0) ? 0.f : xv - xm;
                if (wp == 0)
                    sx128[row] = (!trans) ? xc[(hc * 64 + row) * 256 + 128]
                                          : xc[128 * 256 + hc * 64 + row];
            }
            __syncthreads();
#pragma unroll 4
            for (int kk = 0; kk < 32; kk++) {
                float a0e = xe[kk * 65 + r2];
                float a1e = xe[kk * 65 + r2 + 32];
                float a0o = xo[kk * 65 + r2];
                float a1o = xo[kk * 65 + r2 + 32];
                ull pa0e = pk2(a0e, a0e), pa1e = pk2(a1e, a1e);
                ull pa0o = pk2(a0o, a0o), pa1o = pk2(a1o, a1o);
                const float* cp = sCc + kk * 32 + cg * 8;
                const float* sp = sCs + kk * 32 + cg * 8;
                ulonglong2 c0 = *(const ulonglong2*)cp;
                ulonglong2 c1 = *(const ulonglong2*)(cp + 4);
                ulonglong2 s0 = *(const ulonglong2*)sp;
                ulonglong2 s1 = *(const ulonglong2*)(sp + 4);
                Tr0[0] = ffma2(pa0e, c0.x, Tr0[0]); Tr0[1] = ffma2(pa0e, c0.y, Tr0[1]);
                Tr0[2] = ffma2(pa0e, c1.x, Tr0[2]); Tr0[3] = ffma2(pa0e, c1.y, Tr0[3]);
                Tr1[0] = ffma2(pa1e, c0.x, Tr1[0]); Tr1[1] = ffma2(pa1e, c0.y, Tr1[1]);
                Tr1[2] = ffma2(pa1e, c1.x, Tr1[2]); Tr1[3] = ffma2(pa1e, c1.y, Tr1[3]);
                Ti0[0] = ffma2(pa0o, s0.x, Ti0[0]); Ti0[1] = ffma2(pa0o, s0.y, Ti0[1]);
                Ti0[2] = ffma2(pa0o, s1.x, Ti0[2]); Ti0[3] = ffma2(pa0o, s1.y, Ti0[3]);
                Ti1[0] = ffma2(pa1o, s0.x, Ti1[0]); Ti1[1] = ffma2(pa1o, s0.y, Ti1[1]);
                Ti1[2] = ffma2(pa1o, s1.x, Ti1[2]); Ti1[3] = ffma2(pa1o, s1.y, Ti1[3]);
            }
        }
        {   // x[128] parity term
            const ull PM = pk2(1.f, -1.f);
            ull px0 = pk2(sx128[r2], sx128[r2]);
            ull px1 = pk2(sx128[r2 + 32], sx128[r2 + 32]);
#pragma unroll
            for (int q = 0; q < 4; q++) {
                Tr0[q] = ffma2(px0, PM, Tr0[q]);
                Tr1[q] = ffma2(px1, PM, Tr1[q]);
            }
        }
        __syncthreads();                  // done reading xe/xo/sCc -> write planes
#pragma unroll
        for (int q = 0; q < 4; q++) {
            sTr[r2 * 18 + cg * 4 + q]        = Tr0[q];
            sTi[r2 * 18 + cg * 4 + q]        = Ti0[q];
            sTr[(r2 + 32) * 18 + cg * 4 + q] = Tr1[q];
            sTi[(r2 + 32) * 18 + cg * 4 + q] = Ti1[q];
        }
        __syncthreads();
        // Phase B (FFMA2-packed)
#pragma unroll 2
        for (int hh = 0; hh < 64; hh++) {
            int h  = hc * 64 + hh;
            int i0 = (k1lo * h) & 255;
            int i1 = (k1hi * h) & 255;
            float c0 = str[i0], s0 = sti[i0];
            float c1 = str[i1], s1 = sti[i1];
            ull c0p = pk2(c0, c0), s0p = pk2(s0, s0), n0p = pk2(-s0, -s0);
            ull c1p = pk2(c1, c1), s1p = pk2(s1, s1), n1p = pk2(-s1, -s1);
            ulonglong2 tr01 = *(const ulonglong2*)(sTr + hh * 18 + cg * 4);
            ulonglong2 tr23 = *(const ulonglong2*)(sTr + hh * 18 + cg * 4 + 2);
            ulonglong2 ti01 = *(const ulonglong2*)(sTi + hh * 18 + cg * 4);
            ulonglong2 ti23 = *(const ulonglong2*)(sTi + hh * 18 + cg * 4 + 2);
#define CM2(Q, TR, TI) \
            xfr0p[Q] = ffma2(TR, c0p, xfr0p[Q]); xfr0p[Q] = ffma2(TI, n0p, xfr0p[Q]); \
            xfi0p[Q] = ffma2(TR, s0p, xfi0p[Q]); xfi0p[Q] = ffma2(TI, c0p, xfi0p[Q]); \
            xfr1p[Q] = ffma2(TR, c1p, xfr1p[Q]); xfr1p[Q] = ffma2(TI, n1p, xfr1p[Q]); \
            xfi1p[Q] = ffma2(TR, s1p, xfi1p[Q]); xfi1p[Q] = ffma2(TI, c1p, xfi1p[Q]);
            CM2(0, tr01.x, ti01.x) CM2(1, tr01.y, ti01.y)
            CM2(2, tr23.x, ti23.x) CM2(3, tr23.y, ti23.y)
#undef CM2
        }
    }
    float4* XF4 = (float4*)(g_XF + (size_t)ch * 4096);
#pragma unroll
    for (int q = 0; q < 4; q++) {
        int k2a = cg * 8 + 2 * q;
        float2 r0 = upk(xfr0p[q]), i0 = upk(xfi0p[q]);
        float2 r1 = upk(xfr1p[q]), i1 = upk(xfi1p[q]);
        XF4[(r2 * 32 + k2a) >> 1]        = make_float4(r0.x, i0.x, r0.y, i0.y);
        XF4[((r2 + 32) * 32 + k2a) >> 1] = make_float4(r1.x, i1.x, r1.y, i1.y);
    }
}

// ---------------- stage 3: mode mix (FFMA2, k2-paired) ----------------------
__global__ __launch_bounds__(256) void k_s3(const float* __restrict__ wAr,
                                            const float* __restrict__ wAi,
                                            const float* __restrict__ wBr,
                                            const float* __restrict__ wBi) {
    __shared__ ull sp[4096];              // sxr 2048 | sxi 2048 (32 KB)
    float* sxr = (float*)sp;
    float* sxi = (float*)(sp + 2048);
    int t  = threadIdx.x;
    int j  = blockIdx.x >> 3;
    int ot = blockIdx.x & 7;
    int o  = ot * 8 + (t >> 5);
    int lane = t & 31;
    int bh   = lane >> 4;                 // 0..1 -> b in {bh*4..bh*4+3}
    int k2a  = (lane & 15) * 2;
    const float* wr; const float* wi; int jw;
    if (j < 32) { wr = wAr; wi = wAi; jw = j; }
    else        { wr = wBr; wi = wBi; jw = j - 32; }
    ull yrp[4], yip[4];
#pragma unroll
    for (int b = 0; b < 4; b++) { yrp[b] = 0ull; yip[b] = 0ull; }
    const float2* XF = (const float2*)g_XF;

    for (int ic = 0; ic < 4; ic++) {
        __syncthreads();
#pragma unroll
        for (int q = 0; q < 16; q++) {
            int flat = q * 256 + t;
            int kl = flat & 31;
            int ii = (flat >> 5) & 15;
            int b  = flat >> 9;
            float2 v = XF[((size_t)(b * 64 + ic * 16 + ii) * 64 + j) * 32 + kl];
            sxr[(b * 16 + ii) * 32 + kl] = v.x;
            sxi[(b * 16 + ii) * 32 + kl] = v.y;
        }
        __syncthreads();
#pragma unroll 4
        for (int ii = 0; ii < 16; ii++) {
            int i = ic * 16 + ii;
            size_t wb = (size_t)(i * 64 + o) * 1024 + jw * 32 + k2a;
            float2 wre2 = *(const float2*)(wr + wb);
            float2 wim2 = *(const float2*)(wi + wb);
            ull wrp  = pk2(wre2.x, wre2.y);
            ull wip  = pk2(wim2.x, wim2.y);
            ull nwip = pk2(-wim2.x, -wim2.y);
#pragma unroll
            for (int bb = 0; bb < 4; bb++) {
                int b = bh * 4 + bb;
                ull xrp = *(const ull*)(sxr + (b * 16 + ii) * 32 + k2a);
                ull xip = *(const ull*)(sxi + (b * 16 + ii) * 32 + k2a);
                yrp[bb] = ffma2(xrp, wrp, yrp[bb]);  yrp[bb] = ffma2(xip, nwip, yrp[bb]);
                yip[bb] = ffma2(xrp, wip, yip[bb]);  yip[bb] = ffma2(xip, wrp,  yip[bb]);
            }
        }
    }
#pragma unroll
    for (int bb = 0; bb < 4; bb++) {
        int b = bh * 4 + bb;
        float2 r = upk(yrp[bb]), im = upk(yip[bb]);
        *(float4*)(g_Y + (((size_t)(b * 64 + o) * 64 + j) * 32 + k2a) * 2) =
            make_float4(r.x, im.x, r.y, im.y);
    }
}

// ---------------- fused stage 4+5 (j-parity folded Phase A) -----------------
// block = (ch, g0 in {0,64}); covers h rows [g0,g0+64) and [g0+128,g0+192).
__global__ __launch_bounds__(128) void k_s4s5(float* __restrict__ out) {
    __shared__ float zsA[64 * 68];
    __shared__ float zsB[64 * 68];
    __shared__ ull reg2u[2304];           // sY planes, later F staging
    __shared__ float str[256], sti[256];
    float* reg2 = (float*)reg2u;
    int t  = threadIdx.x;
    int ch = blockIdx.x >> 1;
    int g0 = (blockIdx.x & 1) << 6;
    str[t] = g_twr[t]; str[t + 128] = g_twr[t + 128];
    sti[t] = g_twi[t]; sti[t + 128] = g_twi[t + 128];

    {   // stage Y -> deinterleaved planes [j][36]
        const float2* Yg = (const float2*)(g_Y + (size_t)ch * 4096);
        float* pYr = reg2;
        float* pYi = reg2 + 2304;
#pragma unroll
        for (int q = 0; q < 16; q++) {
            int flat = q * 128 + t;
            int jj = flat >> 5, kl = flat & 31;
            float2 v = Yg[flat];
            pYr[jj * 36 + kl] = v.x;
            pYi[jj * 36 + kl] = v.y;
        }
    }
    __syncthreads();
    ull* sYr = reg2u;
    ull* sYi = reg2u + 1152;

    int hp = t >> 2;                      // 0..31
    int cg = t & 3;
    int hA = g0 + hp;
    ull ze0r[4], ze0i[4], zo0r[4], zo0i[4];   // h = hA
    ull ze1r[4], ze1i[4], zo1r[4], zo1i[4];   // h = hA+32
#pragma unroll
    for (int q = 0; q < 4; q++) {
        ze0r[q]=0ull; ze0i[q]=0ull; zo0r[q]=0ull; zo0i[q]=0ull;
        ze1r[q]=0ull; ze1i[q]=0ull; zo1r[q]=0ull; zo1i[q]=0ull;
    }

#pragma unroll 2
    for (int jp = 0; jp < 32; jp++) {
#define ZACC(R0, I0, R1, I1, J) { \
        int k1 = ((J) < 32) ? (J) : 192 + (J); \
        int ia = (k1 * hA) & 255; \
        int ib = (ia + k1 * 32) & 255; \
        float ca = str[ia], sa = sti[ia]; \
        float cb = str[ib], sb = sti[ib]; \
        ull cap = pk2(ca, ca), sap = pk2(sa, sa), nap = pk2(-sa, -sa); \
        ull cbp = pk2(cb, cb), sbp = pk2(sb, sb), nbp = pk2(-sb, -sb); \
        ulonglong2 yr01 = *(const ulonglong2*)(sYr + (J) * 18 + cg * 4); \
        ulonglong2 yr23 = *(const ulonglong2*)(sYr + (J) * 18 + cg * 4 + 2); \
        ulonglong2 yi01 = *(const ulonglong2*)(sYi + (J) * 18 + cg * 4); \
        ulonglong2 yi23 = *(const ulonglong2*)(sYi + (J) * 18 + cg * 4 + 2); \
        R0[0]=ffma2(yr01.x,cap,R0[0]); R0[0]=ffma2(yi01.x,sap,R0[0]); \
        I0[0]=ffma2(yi01.x,cap,I0[0]); I0[0]=ffma2(yr01.x,nap,I0[0]); \
        R1[0]=ffma2(yr01.x,cbp,R1[0]); R1[0]=ffma2(yi01.x,sbp,R1[0]); \
        I1[0]=ffma2(yi01.x,cbp,I1[0]); I1[0]=ffma2(yr01.x,nbp,I1[0]); \
        R0[1]=ffma2(yr01.y,cap,R0[1]); R0[1]=ffma2(yi01.y,sap,R0[1]); \
        I0[1]=ffma2(yi01.y,cap,I0[1]); I0[1]=ffma2(yr01.y,nap,I0[1]); \
        R1[1]=ffma2(yr01.y,cbp,R1[1]); R1[1]=ffma2(yi01.y,sbp,R1[1]); \
        I1[1]=ffma2(yi01.y,cbp,I1[1]); I1[1]=ffma2(yr01.y,nbp,I1[1]); \
        R0[2]=ffma2(yr23.x,cap,R0[2]); R0[2]=ffma2(yi23.x,sap,R0[2]); \
        I0[2]=ffma2(yi23.x,cap,I0[2]); I0[2]=ffma2(yr23.x,nap,I0[2]); \
        R1[2]=ffma2(yr23.x,cbp,R1[2]); R1[2]=ffma2(yi23.x,sbp,R1[2]); \
        I1[2]=ffma2(yi23.x,cbp,I1[2]); I1[2]=ffma2(yr23.x,nbp,I1[2]); \
        R0[3]=ffma2(yr23.y,cap,R0[3]); R0[3]=ffma2(yi23.y,sap,R0[3]); \
        I0[3]=ffma2(yi23.y,cap,I0[3]); I0[3]=ffma2(yr23.y,nap,I0[3]); \
        R1[3]=ffma2(yr23.y,cbp,R1[3]); R1[3]=ffma2(yi23.y,sbp,R1[3]); \
        I1[3]=ffma2(yi23.y,cbp,I1[3]); I1[3]=ffma2(yr23.y,nbp,I1[3]); }
        ZACC(ze0r, ze0i, ze1r, ze1i, 2 * jp)
        ZACC(zo0r, zo0i, zo1r, zo1i, 2 * jp + 1)
#undef ZACC
    }
    // combine parity partials -> both h tiles
    {
        const ull M1 = pk2(-1.f, -1.f);
#pragma unroll
        for (int q = 0; q < 4; q++) {
            int c2 = 2 * (cg * 8 + 2 * q);
            float2 ra, ia, rb, ib;
            ra = upk(add2(ze0r[q], zo0r[q]));  ia = upk(add2(ze0i[q], zo0i[q]));
            rb = upk(ffma2(zo0r[q], M1, ze0r[q]));  ib = upk(ffma2(zo0i[q], M1, ze0i[q]));
            zsA[c2 * 68 + hp]       = ra.x; zsA[(c2 + 1) * 68 + hp] = ia.x;
            zsA[(c2 + 2) * 68 + hp] = ra.y; zsA[(c2 + 3) * 68 + hp] = ia.y;
            zsB[c2 * 68 + hp]       = rb.x; zsB[(c2 + 1) * 68 + hp] = ib.x;
            zsB[(c2 + 2) * 68 + hp] = rb.y; zsB[(c2 + 3) * 68 + hp] = ib.y;
            ra = upk(add2(ze1r[q], zo1r[q]));  ia = upk(add2(ze1i[q], zo1i[q]));
            rb = upk(ffma2(zo1r[q], M1, ze1r[q]));  ib = upk(ffma2(zo1i[q], M1, ze1i[q]));
            zsA[c2 * 68 + hp + 32]       = ra.x; zsA[(c2 + 1) * 68 + hp + 32] = ia.x;
            zsA[(c2 + 2) * 68 + hp + 32] = ra.y; zsA[(c2 + 3) * 68 + hp + 32] = ia.y;
            zsB[c2 * 68 + hp + 32]       = rb.x; zsB[(c2 + 1) * 68 + hp + 32] = ib.x;
            zsB[(c2 + 2) * 68 + hp + 32] = rb.y; zsB[(c2 + 3) * 68 + hp + 32] = ib.y;
        }
    }
    __syncthreads();

    // w=128 columns for both tiles
    if (t < 64) {
        float sA = zsA[t], sB = zsB[t];
#pragma unroll
        for (int k2 = 1; k2 < 32; k2++) {
            float f = (k2 & 1) ? -2.f : 2.f;
            sA += f * zsA[2 * k2 * 68 + t];
            sB += f * zsB[2 * k2 * 68 + t];
        }
        out[((size_t)ch * 256 + g0 + t) * 256 + 128]       = sA * (1.f / 65536.f);
        out[((size_t)ch * 256 + g0 + 128 + t) * 256 + 128] = sB * (1.f / 65536.f);
    }

    // Phase B: folded inverse-w on both tiles
    int hg = t >> 3;
    int wg = t & 7;
    const float4* FcG = (const float4*)g_Fc;
    const float4* FsG = (const float4*)g_Fs;
    const ull M1 = pk2(-1.f, -1.f);
    for (int wt = 0; wt < 2; wt++) {
        __syncthreads();
        float4* fd = (float4*)reg2;
#pragma unroll
        for (int q = 0; q < 4; q++) {
            int flat = q * 128 + t;
            int k2 = flat >> 4, u = flat & 15;
            fd[k2 * 16 + u]       = FcG[k2 * 32 + wt * 16 + u];
            fd[512 + k2 * 16 + u] = FsG[k2 * 32 + wt * 16 + u];
        }
        __syncthreads();
        for (int tile = 0; tile < 2; tile++) {
            const float* zs = tile ? zsB : zsA;
            int hbase = g0 + tile * 128;
            ull P[16], Q[16];
#pragma unroll
            for (int q = 0; q < 16; q++) { P[q] = 0ull; Q[q] = 0ull; }
#pragma unroll 4
            for (int k2 = 0; k2 < 32; k2++) {
                float4 a = *(const float4*)(zs + (2 * k2) * 68 + hg * 4);
                float4 b = *(const float4*)(zs + (2 * k2 + 1) * 68 + hg * 4);
                const float* fp = reg2 + k2 * 64 + wg * 8;
                ulonglong2 f0 = *(const ulonglong2*)fp;
                ulonglong2 f1 = *(const ulonglong2*)(fp + 4);
                ulonglong2 g0v = *(const ulonglong2*)(fp + 2048);
                ulonglong2 g1v = *(const ulonglong2*)(fp + 2052);
                ull pr, pi;
#define BROW(R, AV, BV) \
                pr = pk2(AV, AV); pi = pk2(BV, BV); \
                P[R*4+0] = ffma2(pr, f0.x, P[R*4+0]); P[R*4+1] = ffma2(pr, f0.y, P[R*4+1]); \
                P[R*4+2] = ffma2(pr, f1.x, P[R*4+2]); P[R*4+3] = ffma2(pr, f1.y, P[R*4+3]); \
                Q[R*4+0] = ffma2(pi, g0v.x, Q[R*4+0]); Q[R*4+1] = ffma2(pi, g0v.y, Q[R*4+1]); \
                Q[R*4+2] = ffma2(pi, g1v.x, Q[R*4+2]); Q[R*4+3] = ffma2(pi, g1v.y, Q[R*4+3]);
                BROW(0, a.x, b.x) BROW(1, a.y, b.y) BROW(2, a.z, b.z) BROW(3, a.w, b.w)
#undef BROW
            }
#pragma unroll
            for (int r = 0; r < 4; r++) {
                int hloc = hg * 4 + r;
                float* orow = out + ((size_t)ch * 256 + hbase + hloc) * 256;
                int wbase = wt * 64 + wg * 8;
                float fw[8], bw[8];
#pragma unroll
                for (int q = 0; q < 4; q++) {
                    ull A  = add2(P[r * 4 + q], Q[r * 4 + q]);
                    ull Bv = ffma2(Q[r * 4 + q], M1, P[r * 4 + q]);
                    float2 fa = upk(A), fb = upk(Bv);
                    fw[2 * q] = fa.x; fw[2 * q + 1] = fa.y;
                    bw[2 * q] = fb.x; bw[2 * q + 1] = fb.y;
                }
                ((float4*)(orow + wbase))[0] = make_float4(fw[0], fw[1], fw[2], fw[3]);
                ((float4*)(orow + wbase))[1] = make_float4(fw[4], fw[5], fw[6], fw[7]);
#pragma unroll
                for (int i = 0; i < 8; i++) {
                    int wv = wbase + i;
                    if (wv) orow[256 - wv] = bw[i];
                }
            }
        }
    }
}

// ---------------------------------------------------------------------------
extern "C" void kernel_launch(void* const* d_in, const int* in_sizes, int n_in,
                              void* d_out, int out_size) {
    const float* x   = (const float*)d_in[0];
    const float* w1r = (const float*)d_in[1];
    const float* w1i = (const float*)d_in[2];
    const float* w2r = (const float*)d_in[3];
    const float* w2i = (const float*)d_in[4];
    const float* w3r = (const float*)d_in[5];
    const float* w3i = (const float*)d_in[6];
    const float* w4r = (const float*)d_in[7];
    const float* w4i = (const float*)d_in[8];
    float* out = (float*)d_out;

    k_init<<<34, 256>>>();

    // ---- branch x ----
    k_s1s2<<<512, 128>>>(x, 0);
    k_s3<<<512, 256>>>(w1r, w1i, w2r, w2i);
    k_s4s5<<<1024, 128>>>(out);

    // ---- branch x^T ----
    k_s1s2<<<512, 128>>>(x, 1);
    k_s3<<<512, 256>>>(w3r, w3i, w4r, w4i);
    k_s4s5<<<1024, 128>>>(out + (size_t)NCH * 65536);
}

// round 6
// speedup vs baseline: 10.7641x; 1.1480x over previous
#include <cuda_runtime.h>

// ---------------------------------------------------------------------------
// SpectralConv2d (FNO). B=8, C=64, H=W=256, M1=M2=32. Two branches.
// v6: 256-thread blocks for occupancy; folds + FFMA2 retained.
// ---------------------------------------------------------------------------

namespace {
constexpr int NCH = 512;           // B*C
}

typedef unsigned long long ull;

__device__ __forceinline__ ull pk2(float lo, float hi) {
    ull r; asm("mov.b64 %0, {%1,%2};" : "=l"(r) : "f"(lo), "f"(hi)); return r;
}
__device__ __forceinline__ ull ffma2(ull a, ull b, ull c) {
    ull d; asm("fma.rn.f32x2 %0, %1, %2, %3;" : "=l"(d) : "l"(a), "l"(b), "l"(c)); return d;
}
__device__ __forceinline__ ull add2(ull a, ull b) {
    ull d; asm("add.rn.f32x2 %0, %1, %2;" : "=l"(d) : "l"(a), "l"(b)); return d;
}
__device__ __forceinline__ float2 upk(ull v) {
    float2 r; asm("mov.b64 {%0,%1}, %2;" : "=f"(r.x), "=f"(r.y) : "l"(v)); return r;
}

__device__ float g_twr[256];
__device__ float g_twi[256];
__device__ float g_Cc[128 * 32];             // cos(2pi k2 w'/256) [w'][k2]
__device__ float g_Cs[128 * 32];             // -sin               [w'][k2]
__device__ float g_Fc[32 * 128];             // sc*(k2?2cos:1)     [k2][w']
__device__ float g_Fs[32 * 128];             // k2? -2sc*sin : 0   [k2][w']
__device__ float g_XF[NCH * 64 * 32 * 2];
__device__ float g_Y [NCH * 64 * 32 * 2];

// ---------------- init ------------------------------------------------------
__global__ void k_init() {
    int idx = blockIdx.x * 256 + threadIdx.x;
    const float sc = 1.0f / 65536.0f;
    if (idx < 256) {
        double s, c;
        sincospi(-2.0 * (double)idx / 256.0, &s, &c);
        g_twr[idx] = (float)c;
        g_twi[idx] = (float)s;
    } else if (idx < 256 + 4096) {
        int j = idx - 256;
        int wp = j >> 5, k2 = j & 31;
        int ang = (k2 * wp) & 255;
        double s, c;
        sincospi(-2.0 * (double)ang / 256.0, &s, &c);
        g_Cc[wp * 32 + k2] = (float)c;
        g_Cs[wp * 32 + k2] = (float)s;
    } else if (idx < 256 + 8192) {
        int j = idx - 4352;
        int k2 = j >> 7, wp = j & 127;
        int ang = (k2 * wp) & 255;
        double s, c;
        sincospi(-2.0 * (double)ang / 256.0, &s, &c);
        g_Fc[k2 * 128 + wp] = (k2 == 0) ? sc : 2.0f * sc * (float)c;
        g_Fs[k2 * 128 + wp] = (k2 == 0) ? 0.0f : 2.0f * sc * (float)s;
    }
}

// ---------------- fused stage 1+2 (256 threads) -----------------------------
// Phase A: thread = (row-pair rp=t>>3 in {rp,rp+32}, k2-group kg=t&7 of 4).
// Phase B: thread = (j-pair {rp, rp+32}, same kg).
__global__ __launch_bounds__(256) void k_s1s2(const float* __restrict__ x, int trans) {
    __shared__ ull bufu[3104];            // A-buffers / Tr,Ti planes (aliased)
    __shared__ float str[256], sti[256];
    __shared__ float sx128[64];
    float* buf = (float*)bufu;
    float* xe  = buf;                     // [32 w'][65]
    float* xo  = buf + 2080;
    float* sCc = buf + 4160;              // [32 kk][32 k2]
    float* sCs = buf + 5184;
    ull* sTr = bufu;                      // [64 h][18 ull]
    ull* sTi = bufu + 1152;

    int t  = threadIdx.x;
    int ch = blockIdx.x;
    const float* xc = x + (size_t)ch * 65536;
    str[t] = g_twr[t];
    sti[t] = g_twi[t];

    int rp = t >> 3;                      // 0..31
    int kg = t & 7;                       // k2 group of 4 (2 ull)
    int k1lo = rp;                        // j = rp
    int k1hi = 224 + rp;                  // j = rp+32 -> k1 = 192+j
    ull xfr0[2], xfi0[2], xfr1[2], xfi1[2];
#pragma unroll
    for (int q = 0; q < 2; q++) { xfr0[q]=0ull; xfi0[q]=0ull; xfr1[q]=0ull; xfi1[q]=0ull; }

    for (int hc = 0; hc < 4; hc++) {
        ull Tr0[2], Ti0[2], Tr1[2], Ti1[2];
#pragma unroll
        for (int q = 0; q < 2; q++) { Tr0[q]=0ull; Ti0[q]=0ull; Tr1[q]=0ull; Ti1[q]=0ull; }

        for (int kc = 0; kc < 4; kc++) {
            __syncthreads();
            ((float4*)sCc)[t] = ((const float4*)(g_Cc + kc * 1024))[t];
            ((float4*)sCs)[t] = ((const float4*)(g_Cs + kc * 1024))[t];
#pragma unroll
            for (int q = 0; q < 8; q++) {
                int flat = q * 256 + t;
                int wl, row;
                if (!trans) { wl = flat & 31; row = flat >> 5; }
                else        { row = flat & 63; wl = flat >> 6; }
                int wp = kc * 32 + wl;
                float xv, xm;
                if (!trans) {
                    xv = xc[(hc * 64 + row) * 256 + wp];
                    xm = (wp == 0) ? 0.f : xc[(hc * 64 + row) * 256 + 256 - wp];
                } else {
                    xv = xc[wp * 256 + hc * 64 + row];
                    xm = (wp == 0) ? 0.f : xc[(256 - wp) * 256 + hc * 64 + row];
                }
                xe[wl * 65 + row] = (wp == 0) ? xv : xv + xm;
                xo[wl * 65 + row] = (wp == 0) ? 0.f : xv - xm;
                if (wp == 0)
                    sx128[row] = (!trans) ? xc[(hc * 64 + row) * 256 + 128]
                                          : xc[128 * 256 + hc * 64 + row];
            }
            __syncthreads();
#pragma unroll 4
            for (int kk = 0; kk < 32; kk++) {
                float a0e = xe[kk * 65 + rp];
                float a1e = xe[kk * 65 + rp + 32];
                float a0o = xo[kk * 65 + rp];
                float a1o = xo[kk * 65 + rp + 32];
                ull pa0e = pk2(a0e, a0e), pa1e = pk2(a1e, a1e);
                ull pa0o = pk2(a0o, a0o), pa1o = pk2(a1o, a1o);
                ulonglong2 c01 = *(const ulonglong2*)(sCc + kk * 32 + kg * 4);
                ulonglong2 s01 = *(const ulonglong2*)(sCs + kk * 32 + kg * 4);
                Tr0[0] = ffma2(pa0e, c01.x, Tr0[0]); Tr0[1] = ffma2(pa0e, c01.y, Tr0[1]);
                Tr1[0] = ffma2(pa1e, c01.x, Tr1[0]); Tr1[1] = ffma2(pa1e, c01.y, Tr1[1]);
                Ti0[0] = ffma2(pa0o, s01.x, Ti0[0]); Ti0[1] = ffma2(pa0o, s01.y, Ti0[1]);
                Ti1[0] = ffma2(pa1o, s01.x, Ti1[0]); Ti1[1] = ffma2(pa1o, s01.y, Ti1[1]);
            }
        }
        {   // x[128] parity term (pairs are (even k2, odd k2))
            const ull PM = pk2(1.f, -1.f);
            ull px0 = pk2(sx128[rp], sx128[rp]);
            ull px1 = pk2(sx128[rp + 32], sx128[rp + 32]);
#pragma unroll
            for (int q = 0; q < 2; q++) {
                Tr0[q] = ffma2(px0, PM, Tr0[q]);
                Tr1[q] = ffma2(px1, PM, Tr1[q]);
            }
        }
        __syncthreads();
#pragma unroll
        for (int q = 0; q < 2; q++) {
            sTr[rp * 18 + kg * 2 + q]        = Tr0[q];
            sTi[rp * 18 + kg * 2 + q]        = Ti0[q];
            sTr[(rp + 32) * 18 + kg * 2 + q] = Tr1[q];
            sTi[(rp + 32) * 18 + kg * 2 + q] = Ti1[q];
        }
        __syncthreads();
        // Phase B
#pragma unroll 2
        for (int hh = 0; hh < 64; hh++) {
            int h  = hc * 64 + hh;
            int i0 = (k1lo * h) & 255;
            int i1 = (k1hi * h) & 255;
            float c0 = str[i0], s0 = sti[i0];
            float c1 = str[i1], s1 = sti[i1];
            ull c0p = pk2(c0, c0), s0p = pk2(s0, s0), n0p = pk2(-s0, -s0);
            ull c1p = pk2(c1, c1), s1p = pk2(s1, s1), n1p = pk2(-s1, -s1);
            ulonglong2 tr = *(const ulonglong2*)(sTr + hh * 18 + kg * 2);
            ulonglong2 ti = *(const ulonglong2*)(sTi + hh * 18 + kg * 2);
#define CM2(Q, TR, TI) \
            xfr0[Q] = ffma2(TR, c0p, xfr0[Q]); xfr0[Q] = ffma2(TI, n0p, xfr0[Q]); \
            xfi0[Q] = ffma2(TR, s0p, xfi0[Q]); xfi0[Q] = ffma2(TI, c0p, xfi0[Q]); \
            xfr1[Q] = ffma2(TR, c1p, xfr1[Q]); xfr1[Q] = ffma2(TI, n1p, xfr1[Q]); \
            xfi1[Q] = ffma2(TR, s1p, xfi1[Q]); xfi1[Q] = ffma2(TI, c1p, xfi1[Q]);
            CM2(0, tr.x, ti.x) CM2(1, tr.y, ti.y)
#undef CM2
        }
    }
    float4* XF4 = (float4*)(g_XF + (size_t)ch * 4096);
    {
        int b0 = rp * 16 + kg * 2;
        int b1 = (rp + 32) * 16 + kg * 2;
        float2 r0 = upk(xfr0[0]), i0 = upk(xfi0[0]);
        float2 r0b = upk(xfr0[1]), i0b = upk(xfi0[1]);
        float2 r1 = upk(xfr1[0]), i1 = upk(xfi1[0]);
        float2 r1b = upk(xfr1[1]), i1b = upk(xfi1[1]);
        XF4[b0]     = make_float4(r0.x, i0.x, r0.y, i0.y);
        XF4[b0 + 1] = make_float4(r0b.x, i0b.x, r0b.y, i0b.y);
        XF4[b1]     = make_float4(r1.x, i1.x, r1.y, i1.y);
        XF4[b1 + 1] = make_float4(r1b.x, i1b.x, r1b.y, i1b.y);
    }
}

// ---------------- stage 3: mode mix (FFMA2, k2-paired) ----------------------
__global__ __launch_bounds__(256) void k_s3(const float* __restrict__ wAr,
                                            const float* __restrict__ wAi,
                                            const float* __restrict__ wBr,
                                            const float* __restrict__ wBi) {
    __shared__ ull sp[4096];              // sxr 2048 | sxi 2048 (32 KB)
    float* sxr = (float*)sp;
    float* sxi = (float*)(sp + 2048);
    int t  = threadIdx.x;
    int j  = blockIdx.x >> 3;
    int ot = blockIdx.x & 7;
    int o  = ot * 8 + (t >> 5);
    int lane = t & 31;
    int bh   = lane >> 4;
    int k2a  = (lane & 15) * 2;
    const float* wr; const float* wi; int jw;
    if (j < 32) { wr = wAr; wi = wAi; jw = j; }
    else        { wr = wBr; wi = wBi; jw = j - 32; }
    ull yrp[4], yip[4];
#pragma unroll
    for (int b = 0; b < 4; b++) { yrp[b] = 0ull; yip[b] = 0ull; }
    const float2* XF = (const float2*)g_XF;

    for (int ic = 0; ic < 4; ic++) {
        __syncthreads();
#pragma unroll
        for (int q = 0; q < 16; q++) {
            int flat = q * 256 + t;
            int kl = flat & 31;
            int ii = (flat >> 5) & 15;
            int b  = flat >> 9;
            float2 v = XF[((size_t)(b * 64 + ic * 16 + ii) * 64 + j) * 32 + kl];
            sxr[(b * 16 + ii) * 32 + kl] = v.x;
            sxi[(b * 16 + ii) * 32 + kl] = v.y;
        }
        __syncthreads();
#pragma unroll 4
        for (int ii = 0; ii < 16; ii++) {
            int i = ic * 16 + ii;
            size_t wb = (size_t)(i * 64 + o) * 1024 + jw * 32 + k2a;
            float2 wre2 = *(const float2*)(wr + wb);
            float2 wim2 = *(const float2*)(wi + wb);
            ull wrp  = pk2(wre2.x, wre2.y);
            ull wip  = pk2(wim2.x, wim2.y);
            ull nwip = pk2(-wim2.x, -wim2.y);
#pragma unroll
            for (int bb = 0; bb < 4; bb++) {
                int b = bh * 4 + bb;
                ull xrp = *(const ull*)(sxr + (b * 16 + ii) * 32 + k2a);
                ull xip = *(const ull*)(sxi + (b * 16 + ii) * 32 + k2a);
                yrp[bb] = ffma2(xrp, wrp, yrp[bb]);  yrp[bb] = ffma2(xip, nwip, yrp[bb]);
                yip[bb] = ffma2(xrp, wip, yip[bb]);  yip[bb] = ffma2(xip, wrp,  yip[bb]);
            }
        }
    }
#pragma unroll
    for (int bb = 0; bb < 4; bb++) {
        int b = bh * 4 + bb;
        float2 r = upk(yrp[bb]), im = upk(yip[bb]);
        *(float4*)(g_Y + (((size_t)(b * 64 + o) * 64 + j) * 32 + k2a) * 2) =
            make_float4(r.x, im.x, r.y, im.y);
    }
}

// ---------------- fused stage 4+5 (256 threads) -----------------------------
// block = (ch, g0 in {0,64}); covers h rows [g0,g0+64) and [g0+128,g0+192).
// Phase A: thread = (h-pair hp=t>>3 -> {g0+hp, g0+hp+32}, kg=t&7 group of 4 k2).
// Phase B: thread = (hg=t>>4 -> 4 h rows, wg=t&15 -> 4 w' cols).
__global__ __launch_bounds__(256) void k_s4s5(float* __restrict__ out) {
    __shared__ float zsA[64 * 68];
    __shared__ float zsB[64 * 68];
    __shared__ ull reg2u[2304];           // sY planes, later F staging
    __shared__ float str[256], sti[256];
    float* reg2 = (float*)reg2u;
    int t  = threadIdx.x;
    int ch = blockIdx.x >> 1;
    int g0 = (blockIdx.x & 1) << 6;
    str[t] = g_twr[t];
    sti[t] = g_twi[t];

    {   // stage Y -> deinterleaved planes [j][36]
        const float2* Yg = (const float2*)(g_Y + (size_t)ch * 4096);
        float* pYr = reg2;
        float* pYi = reg2 + 2304;
#pragma unroll
        for (int q = 0; q < 8; q++) {
            int flat = q * 256 + t;
            int jj = flat >> 5, kl = flat & 31;
            float2 v = Yg[flat];
            pYr[jj * 36 + kl] = v.x;
            pYi[jj * 36 + kl] = v.y;
        }
    }
    __syncthreads();
    ull* sYr = reg2u;
    ull* sYi = reg2u + 1152;

    int hp = t >> 3;                      // 0..31
    int kg = t & 7;                       // k2 group of 4 (2 ull)
    int hA = g0 + hp;
    ull ze0r[2], ze0i[2], zo0r[2], zo0i[2];   // h = hA
    ull ze1r[2], ze1i[2], zo1r[2], zo1i[2];   // h = hA+32
#pragma unroll
    for (int q = 0; q < 2; q++) {
        ze0r[q]=0ull; ze0i[q]=0ull; zo0r[q]=0ull; zo0i[q]=0ull;
        ze1r[q]=0ull; ze1i[q]=0ull; zo1r[q]=0ull; zo1i[q]=0ull;
    }

#pragma unroll 2
    for (int jp = 0; jp < 32; jp++) {
#define ZACC(R0, I0, R1, I1, J) { \
        int k1 = ((J) < 32) ? (J) : 192 + (J); \
        int ia = (k1 * hA) & 255; \
        int ib = (ia + k1 * 32) & 255; \
        float ca = str[ia], sa = sti[ia]; \
        float cb = str[ib], sb = sti[ib]; \
        ull cap = pk2(ca, ca), sap = pk2(sa, sa), nap = pk2(-sa, -sa); \
        ull cbp = pk2(cb, cb), sbp = pk2(sb, sb), nbp = pk2(-sb, -sb); \
        ulonglong2 yr = *(const ulonglong2*)(sYr + (J) * 18 + kg * 2); \
        ulonglong2 yi = *(const ulonglong2*)(sYi + (J) * 18 + kg * 2); \
        R0[0]=ffma2(yr.x,cap,R0[0]); R0[0]=ffma2(yi.x,sap,R0[0]); \
        I0[0]=ffma2(yi.x,cap,I0[0]); I0[0]=ffma2(yr.x,nap,I0[0]); \
        R0[1]=ffma2(yr.y,cap,R0[1]); R0[1]=ffma2(yi.y,sap,R0[1]); \
        I0[1]=ffma2(yi.y,cap,I0[1]); I0[1]=ffma2(yr.y,nap,I0[1]); \
        R1[0]=ffma2(yr.x,cbp,R1[0]); R1[0]=ffma2(yi.x,sbp,R1[0]); \
        I1[0]=ffma2(yi.x,cbp,I1[0]); I1[0]=ffma2(yr.x,nbp,I1[0]); \
        R1[1]=ffma2(yr.y,cbp,R1[1]); R1[1]=ffma2(yi.y,sbp,R1[1]); \
        I1[1]=ffma2(yi.y,cbp,I1[1]); I1[1]=ffma2(yr.y,nbp,I1[1]); }
        ZACC(ze0r, ze0i, ze1r, ze1i, 2 * jp)
        ZACC(zo0r, zo0i, zo1r, zo1i, 2 * jp + 1)
#undef ZACC
    }
    // combine parity partials -> both h tiles
    {
        const ull M1 = pk2(-1.f, -1.f);
#pragma unroll
        for (int q = 0; q < 2; q++) {
            int c2 = 2 * (kg * 4 + 2 * q);
            float2 ra, ia, rb, ib;
            ra = upk(add2(ze0r[q], zo0r[q]));  ia = upk(add2(ze0i[q], zo0i[q]));
            rb = upk(ffma2(zo0r[q], M1, ze0r[q]));  ib = upk(ffma2(zo0i[q], M1, ze0i[q]));
            zsA[c2 * 68 + hp]       = ra.x; zsA[(c2 + 1) * 68 + hp] = ia.x;
            zsA[(c2 + 2) * 68 + hp] = ra.y; zsA[(c2 + 3) * 68 + hp] = ia.y;
            zsB[c2 * 68 + hp]       = rb.x; zsB[(c2 + 1) * 68 + hp] = ib.x;
            zsB[(c2 + 2) * 68 + hp] = rb.y; zsB[(c2 + 3) * 68 + hp] = ib.y;
            ra = upk(add2(ze1r[q], zo1r[q]));  ia = upk(add2(ze1i[q], zo1i[q]));
            rb = upk(ffma2(zo1r[q], M1, ze1r[q]));  ib = upk(ffma2(zo1i[q], M1, ze1i[q]));
            zsA[c2 * 68 + hp + 32]       = ra.x; zsA[(c2 + 1) * 68 + hp + 32] = ia.x;
            zsA[(c2 + 2) * 68 + hp + 32] = ra.y; zsA[(c2 + 3) * 68 + hp + 32] = ia.y;
            zsB[c2 * 68 + hp + 32]       = rb.x; zsB[(c2 + 1) * 68 + hp + 32] = ib.x;
            zsB[(c2 + 2) * 68 + hp + 32] = rb.y; zsB[(c2 + 3) * 68 + hp + 32] = ib.y;
        }
    }
    __syncthreads();

    // w=128 columns for both tiles
    if (t < 128) {
        int tile = t >> 6;
        int row  = t & 63;
        const float* zz = tile ? zsB : zsA;
        float s = zz[row];
#pragma unroll
        for (int k2 = 1; k2 < 32; k2++)
            s += ((k2 & 1) ? -2.f : 2.f) * zz[2 * k2 * 68 + row];
        out[((size_t)ch * 256 + g0 + tile * 128 + row) * 256 + 128] = s * (1.f / 65536.f);
    }

    // Phase B: folded inverse-w on both tiles
    int hg = t >> 4;                      // 0..15 -> 4 h rows
    int wg = t & 15;                      // 4 w' cols
    const float4* FcG = (const float4*)g_Fc;
    const float4* FsG = (const float4*)g_Fs;
    const ull M1 = pk2(-1.f, -1.f);
    for (int wt = 0; wt < 2; wt++) {
        __syncthreads();
        float4* fd = (float4*)reg2;
#pragma unroll
        for (int q = 0; q < 2; q++) {
            int flat = q * 256 + t;
            int k2 = flat >> 4, u = flat & 15;
            fd[k2 * 16 + u]       = FcG[k2 * 32 + wt * 16 + u];
            fd[512 + k2 * 16 + u] = FsG[k2 * 32 + wt * 16 + u];
        }
        __syncthreads();
        for (int tile = 0; tile < 2; tile++) {
            const float* zs = tile ? zsB : zsA;
            int hbase = g0 + tile * 128;
            ull P[8], Q[8];
#pragma unroll
            for (int q = 0; q < 8; q++) { P[q] = 0ull; Q[q] = 0ull; }
#pragma unroll 4
            for (int k2 = 0; k2 < 32; k2++) {
                float4 a = *(const float4*)(zs + (2 * k2) * 68 + hg * 4);
                float4 b = *(const float4*)(zs + (2 * k2 + 1) * 68 + hg * 4);
                const float* fp = reg2 + k2 * 64 + wg * 4;
                ulonglong2 f = *(const ulonglong2*)fp;
                ulonglong2 g = *(const ulonglong2*)(fp + 2048);
                ull pr, pi;
#define BROW(R, AV, BV) \
                pr = pk2(AV, AV); pi = pk2(BV, BV); \
                P[R*2+0] = ffma2(pr, f.x, P[R*2+0]); P[R*2+1] = ffma2(pr, f.y, P[R*2+1]); \
                Q[R*2+0] = ffma2(pi, g.x, Q[R*2+0]); Q[R*2+1] = ffma2(pi, g.y, Q[R*2+1]);
                BROW(0, a.x, b.x) BROW(1, a.y, b.y) BROW(2, a.z, b.z) BROW(3, a.w, b.w)
#undef BROW
            }
#pragma unroll
            for (int r = 0; r < 4; r++) {
                int hloc = hg * 4 + r;
                float* orow = out + ((size_t)ch * 256 + hbase + hloc) * 256;
                int wbase = wt * 64 + wg * 4;
                ull A0 = add2(P[r * 2], Q[r * 2]);
                ull A1 = add2(P[r * 2 + 1], Q[r * 2 + 1]);
                ull B0 = ffma2(Q[r * 2], M1, P[r * 2]);
                ull B1 = ffma2(Q[r * 2 + 1], M1, P[r * 2 + 1]);
                float2 fa0 = upk(A0), fa1 = upk(A1);
                float2 fb0 = upk(B0), fb1 = upk(B1);
                *(float4*)(orow + wbase) = make_float4(fa0.x, fa0.y, fa1.x, fa1.y);
                float bw[4] = {fb0.x, fb0.y, fb1.x, fb1.y};
#pragma unroll
                for (int i = 0; i < 4; i++) {
                    int wv = wbase + i;
                    if (wv) orow[256 - wv] = bw[i];
                }
            }
        }
    }
}

// ---------------------------------------------------------------------------
extern "C" void kernel_launch(void* const* d_in, const int* in_sizes, int n_in,
                              void* d_out, int out_size) {
    const float* x   = (const float*)d_in[0];
    const float* w1r = (const float*)d_in[1];
    const float* w1i = (const float*)d_in[2];
    const float* w2r = (const float*)d_in[3];
    const float* w2i = (const float*)d_in[4];
    const float* w3r = (const float*)d_in[5];
    const float* w3i = (const float*)d_in[6];
    const float* w4r = (const float*)d_in[7];
    const float* w4i = (const float*)d_in[8];
    float* out = (float*)d_out;

    k_init<<<34, 256>>>();

    // ---- branch x ----
    k_s1s2<<<512, 256>>>(x, 0);
    k_s3<<<512, 256>>>(w1r, w1i, w2r, w2i);
    k_s4s5<<<1024, 256>>>(out);

    // ---- branch x^T ----
    k_s1s2<<<512, 256>>>(x, 1);
    k_s3<<<512, 256>>>(w3r, w3i, w4r, w4i);
    k_s4s5<<<1024, 256>>>(out + (size_t)NCH * 65536);
}

// round 7
// speedup vs baseline: 10.9415x; 1.0165x over previous
#include <cuda_runtime.h>

// ---------------------------------------------------------------------------
// SpectralConv2d (FNO). B=8, C=64, H=W=256, M1=M2=32. Two branches.
// v7: +-k conjugate pairing in both h-DFTs (halves their FMA count).
// ---------------------------------------------------------------------------

namespace {
constexpr int NCH = 512;           // B*C
}

typedef unsigned long long ull;

__device__ __forceinline__ ull pk2(float lo, float hi) {
    ull r; asm("mov.b64 %0, {%1,%2};" : "=l"(r) : "f"(lo), "f"(hi)); return r;
}
__device__ __forceinline__ ull ffma2(ull a, ull b, ull c) {
    ull d; asm("fma.rn.f32x2 %0, %1, %2, %3;" : "=l"(d) : "l"(a), "l"(b), "l"(c)); return d;
}
__device__ __forceinline__ ull add2(ull a, ull b) {
    ull d; asm("add.rn.f32x2 %0, %1, %2;" : "=l"(d) : "l"(a), "l"(b)); return d;
}
__device__ __forceinline__ float2 upk(ull v) {
    float2 r; asm("mov.b64 {%0,%1}, %2;" : "=f"(r.x), "=f"(r.y) : "l"(v)); return r;
}

__device__ float g_twr[256];
__device__ float g_twi[256];
__device__ float g_Cc[128 * 32];             // cos(2pi k2 w'/256) [w'][k2]
__device__ float g_Cs[128 * 32];             // -sin               [w'][k2]
__device__ float g_Fc[32 * 128];             // sc*(k2?2cos:1)     [k2][w']
__device__ float g_Fs[32 * 128];             // k2? -2sc*sin : 0   [k2][w']
__device__ float g_XF[NCH * 64 * 32 * 2];
__device__ float g_Y [NCH * 64 * 32 * 2];

// ---------------- init ------------------------------------------------------
__global__ void k_init() {
    int idx = blockIdx.x * 256 + threadIdx.x;
    const float sc = 1.0f / 65536.0f;
    if (idx < 256) {
        double s, c;
        sincospi(-2.0 * (double)idx / 256.0, &s, &c);
        g_twr[idx] = (float)c;
        g_twi[idx] = (float)s;
    } else if (idx < 256 + 4096) {
        int j = idx - 256;
        int wp = j >> 5, k2 = j & 31;
        int ang = (k2 * wp) & 255;
        double s, c;
        sincospi(-2.0 * (double)ang / 256.0, &s, &c);
        g_Cc[wp * 32 + k2] = (float)c;
        g_Cs[wp * 32 + k2] = (float)s;
    } else if (idx < 256 + 8192) {
        int j = idx - 4352;
        int k2 = j >> 7, wp = j & 127;
        int ang = (k2 * wp) & 255;
        double s, c;
        sincospi(-2.0 * (double)ang / 256.0, &s, &c);
        g_Fc[k2 * 128 + wp] = (k2 == 0) ? sc : 2.0f * sc * (float)c;
        g_Fs[k2 * 128 + wp] = (k2 == 0) ? 0.0f : 2.0f * sc * (float)s;
    }
}

// ---------------- fused stage 1+2 (256 threads) -----------------------------
// Phase A: thread = (row-pair rp in {rp,rp+32}, k2-group kg of 4).
// Phase B (+-k paired): thread rp covers j=rp (k1=+rp) and j=64-rp (k1=-rp);
//   rp==0 covers j=0 (running sum) and j=32 (k1=-32, base angle 32h).
__global__ __launch_bounds__(256) void k_s1s2(const float* __restrict__ x, int trans) {
    __shared__ ull bufu[3104];            // A-buffers / Tr,Ti planes (aliased)
    __shared__ float str[256], sti[256];
    __shared__ float sx128[64];
    float* buf = (float*)bufu;
    float* xe  = buf;                     // [32 w'][65]
    float* xo  = buf + 2080;
    float* sCc = buf + 4160;              // [32 kk][32 k2]
    float* sCs = buf + 5184;
    ull* sTr = bufu;                      // [64 h][18 ull]
    ull* sTi = bufu + 1152;

    int t  = threadIdx.x;
    int ch = blockIdx.x;
    const float* xc = x + (size_t)ch * 65536;
    str[t] = g_twr[t];
    sti[t] = g_twi[t];

    int rp = t >> 3;                      // 0..31
    int kg = t & 7;                       // k2 group of 4 (2 ull)
    int m  = rp ? rp : 32;                // twiddle base multiplier
    ull Aq[2], Bq[2], Cq[2], Dq[2], SrA[2], SiA[2];
#pragma unroll
    for (int q = 0; q < 2; q++) { Aq[q]=0ull; Bq[q]=0ull; Cq[q]=0ull; Dq[q]=0ull; SrA[q]=0ull; SiA[q]=0ull; }

    for (int hc = 0; hc < 4; hc++) {
        ull Tr0[2], Ti0[2], Tr1[2], Ti1[2];
#pragma unroll
        for (int q = 0; q < 2; q++) { Tr0[q]=0ull; Ti0[q]=0ull; Tr1[q]=0ull; Ti1[q]=0ull; }

        for (int kc = 0; kc < 4; kc++) {
            __syncthreads();
            ((float4*)sCc)[t] = ((const float4*)(g_Cc + kc * 1024))[t];
            ((float4*)sCs)[t] = ((const float4*)(g_Cs + kc * 1024))[t];
#pragma unroll
            for (int q = 0; q < 8; q++) {
                int flat = q * 256 + t;
                int wl, row;
                if (!trans) { wl = flat & 31; row = flat >> 5; }
                else        { row = flat & 63; wl = flat >> 6; }
                int wp = kc * 32 + wl;
                float xv, xm;
                if (!trans) {
                    xv = xc[(hc * 64 + row) * 256 + wp];
                    xm = (wp == 0) ? 0.f : xc[(hc * 64 + row) * 256 + 256 - wp];
                } else {
                    xv = xc[wp * 256 + hc * 64 + row];
                    xm = (wp == 0) ? 0.f : xc[(256 - wp) * 256 + hc * 64 + row];
                }
                xe[wl * 65 + row] = (wp == 0) ? xv : xv + xm;
                xo[wl * 65 + row] = (wp == 0) ? 0.f : xv - xm;
                if (wp == 0)
                    sx128[row] = (!trans) ? xc[(hc * 64 + row) * 256 + 128]
                                          : xc[128 * 256 + hc * 64 + row];
            }
            __syncthreads();
#pragma unroll 4
            for (int kk = 0; kk < 32; kk++) {
                float a0e = xe[kk * 65 + rp];
                float a1e = xe[kk * 65 + rp + 32];
                float a0o = xo[kk * 65 + rp];
                float a1o = xo[kk * 65 + rp + 32];
                ull pa0e = pk2(a0e, a0e), pa1e = pk2(a1e, a1e);
                ull pa0o = pk2(a0o, a0o), pa1o = pk2(a1o, a1o);
                ulonglong2 c01 = *(const ulonglong2*)(sCc + kk * 32 + kg * 4);
                ulonglong2 s01 = *(const ulonglong2*)(sCs + kk * 32 + kg * 4);
                Tr0[0] = ffma2(pa0e, c01.x, Tr0[0]); Tr0[1] = ffma2(pa0e, c01.y, Tr0[1]);
                Tr1[0] = ffma2(pa1e, c01.x, Tr1[0]); Tr1[1] = ffma2(pa1e, c01.y, Tr1[1]);
                Ti0[0] = ffma2(pa0o, s01.x, Ti0[0]); Ti0[1] = ffma2(pa0o, s01.y, Ti0[1]);
                Ti1[0] = ffma2(pa1o, s01.x, Ti1[0]); Ti1[1] = ffma2(pa1o, s01.y, Ti1[1]);
            }
        }
        {   // x[128] parity term (pairs are (even k2, odd k2))
            const ull PM = pk2(1.f, -1.f);
            ull px0 = pk2(sx128[rp], sx128[rp]);
            ull px1 = pk2(sx128[rp + 32], sx128[rp + 32]);
#pragma unroll
            for (int q = 0; q < 2; q++) {
                Tr0[q] = ffma2(px0, PM, Tr0[q]);
                Tr1[q] = ffma2(px1, PM, Tr1[q]);
            }
        }
        __syncthreads();
#pragma unroll
        for (int q = 0; q < 2; q++) {
            sTr[rp * 18 + kg * 2 + q]        = Tr0[q];
            sTi[rp * 18 + kg * 2 + q]        = Ti0[q];
            sTr[(rp + 32) * 18 + kg * 2 + q] = Tr1[q];
            sTi[(rp + 32) * 18 + kg * 2 + q] = Ti1[q];
        }
        __syncthreads();
        // Phase B: accumulate A,B',C',D at base angle m*h
#pragma unroll 2
        for (int hh = 0; hh < 64; hh++) {
            int h   = hc * 64 + hh;
            int idx = (m * h) & 255;
            float c = str[idx], s = sti[idx];
            ull cp = pk2(c, c), sp = pk2(s, s);
            ulonglong2 tr = *(const ulonglong2*)(sTr + hh * 18 + kg * 2);
            ulonglong2 ti = *(const ulonglong2*)(sTi + hh * 18 + kg * 2);
            Aq[0] = ffma2(tr.x, cp, Aq[0]); Cq[0] = ffma2(tr.x, sp, Cq[0]);
            Dq[0] = ffma2(ti.x, cp, Dq[0]); Bq[0] = ffma2(ti.x, sp, Bq[0]);
            Aq[1] = ffma2(tr.y, cp, Aq[1]); Cq[1] = ffma2(tr.y, sp, Cq[1]);
            Dq[1] = ffma2(ti.y, cp, Dq[1]); Bq[1] = ffma2(ti.y, sp, Bq[1]);
            if (rp == 0) {
                SrA[0] = add2(SrA[0], tr.x); SrA[1] = add2(SrA[1], tr.y);
                SiA[0] = add2(SiA[0], ti.x); SiA[1] = add2(SiA[1], ti.y);
            }
        }
    }
    // combine: XF(+k) = (A-B', D+C'); XF(-k) = (A+B', D-C'); rp==0: j0 = S, j32 = -32 slot
    {
        const ull M1 = pk2(-1.f, -1.f);
        float4* XF4 = (float4*)(g_XF + (size_t)ch * 4096);
        int jhi = rp ? (64 - rp) : 32;
#pragma unroll
        for (int q = 0; q < 2; q++) {
            ull rhi = add2(Aq[q], Bq[q]);
            ull ihi = ffma2(Cq[q], M1, Dq[q]);
            ull rlo = rp ? ffma2(Bq[q], M1, Aq[q]) : SrA[q];
            ull ilo = rp ? add2(Dq[q], Cq[q])      : SiA[q];
            float2 a = upk(rlo), b = upk(ilo);
            float2 cc = upk(rhi), d = upk(ihi);
            XF4[rp * 16 + kg * 2 + q]  = make_float4(a.x, b.x, a.y, b.y);
            XF4[jhi * 16 + kg * 2 + q] = make_float4(cc.x, d.x, cc.y, d.y);
        }
    }
}

// ---------------- stage 3: mode mix (FFMA2, k2-paired) ----------------------
__global__ __launch_bounds__(256) void k_s3(const float* __restrict__ wAr,
                                            const float* __restrict__ wAi,
                                            const float* __restrict__ wBr,
                                            const float* __restrict__ wBi) {
    __shared__ ull sp[4096];              // sxr 2048 | sxi 2048 (32 KB)
    float* sxr = (float*)sp;
    float* sxi = (float*)(sp + 2048);
    int t  = threadIdx.x;
    int j  = blockIdx.x >> 3;
    int ot = blockIdx.x & 7;
    int o  = ot * 8 + (t >> 5);
    int lane = t & 31;
    int bh   = lane >> 4;
    int k2a  = (lane & 15) * 2;
    const float* wr; const float* wi; int jw;
    if (j < 32) { wr = wAr; wi = wAi; jw = j; }
    else        { wr = wBr; wi = wBi; jw = j - 32; }
    ull yrp[4], yip[4];
#pragma unroll
    for (int b = 0; b < 4; b++) { yrp[b] = 0ull; yip[b] = 0ull; }
    const float2* XF = (const float2*)g_XF;

    for (int ic = 0; ic < 4; ic++) {
        __syncthreads();
#pragma unroll
        for (int q = 0; q < 16; q++) {
            int flat = q * 256 + t;
            int kl = flat & 31;
            int ii = (flat >> 5) & 15;
            int b  = flat >> 9;
            float2 v = XF[((size_t)(b * 64 + ic * 16 + ii) * 64 + j) * 32 + kl];
            sxr[(b * 16 + ii) * 32 + kl] = v.x;
            sxi[(b * 16 + ii) * 32 + kl] = v.y;
        }
        __syncthreads();
#pragma unroll 4
        for (int ii = 0; ii < 16; ii++) {
            int i = ic * 16 + ii;
            size_t wb = (size_t)(i * 64 + o) * 1024 + jw * 32 + k2a;
            float2 wre2 = *(const float2*)(wr + wb);
            float2 wim2 = *(const float2*)(wi + wb);
            ull wrp  = pk2(wre2.x, wre2.y);
            ull wip  = pk2(wim2.x, wim2.y);
            ull nwip = pk2(-wim2.x, -wim2.y);
#pragma unroll
            for (int bb = 0; bb < 4; bb++) {
                int b = bh * 4 + bb;
                ull xrp = *(const ull*)(sxr + (b * 16 + ii) * 32 + k2a);
                ull xip = *(const ull*)(sxi + (b * 16 + ii) * 32 + k2a);
                yrp[bb] = ffma2(xrp, wrp, yrp[bb]);  yrp[bb] = ffma2(xip, nwip, yrp[bb]);
                yip[bb] = ffma2(xrp, wip, yip[bb]);  yip[bb] = ffma2(xip, wrp,  yip[bb]);
            }
        }
    }
#pragma unroll
    for (int bb = 0; bb < 4; bb++) {
        int b = bh * 4 + bb;
        float2 r = upk(yrp[bb]), im = upk(yip[bb]);
        *(float4*)(g_Y + (((size_t)(b * 64 + o) * 64 + j) * 32 + k2a) * 2) =
            make_float4(r.x, im.x, r.y, im.y);
    }
}

// ---------------- fused stage 4+5 (256 threads, +-j paired Phase A) ---------
// block = (ch, g0 in {0,64}); covers h rows [g0,g0+64) and [g0+128,g0+192).
__global__ __launch_bounds__(256) void k_s4s5(float* __restrict__ out) {
    __shared__ float zsA[64 * 68];
    __shared__ float zsB[64 * 68];
    __shared__ ull reg2u[2304];           // sY planes (E/O transformed), later F staging
    __shared__ float str[256], sti[256];
    float* reg2 = (float*)reg2u;
    int t  = threadIdx.x;
    int ch = blockIdx.x >> 1;
    int g0 = (blockIdx.x & 1) << 6;
    str[t] = g_twr[t];
    sti[t] = g_twi[t];

    float* pYr = reg2;                    // [j][36]
    float* pYi = reg2 + 2304;
    {   // stage Y -> deinterleaved planes
        const float2* Yg = (const float2*)(g_Y + (size_t)ch * 4096);
#pragma unroll
        for (int q = 0; q < 8; q++) {
            int flat = q * 256 + t;
            int jj = flat >> 5, kl = flat & 31;
            float2 v = Yg[flat];
            pYr[jj * 36 + kl] = v.x;
            pYi[jj * 36 + kl] = v.y;
        }
    }
    __syncthreads();
    {   // E/O transform in place: row a <- Y[a]+Y[64-a], row 64-a <- Y[a]-Y[64-a]
#pragma unroll
        for (int q = 0; q < 4; q++) {
            int flat = q * 256 + t;
            if (flat < 992) {
                int a = (flat >> 5) + 1;
                int col = flat & 31;
                float ya = pYr[a * 36 + col], yb = pYr[(64 - a) * 36 + col];
                pYr[a * 36 + col] = ya + yb;
                pYr[(64 - a) * 36 + col] = ya - yb;
                float za = pYi[a * 36 + col], zb = pYi[(64 - a) * 36 + col];
                pYi[a * 36 + col] = za + zb;
                pYi[(64 - a) * 36 + col] = za - zb;
            }
        }
    }
    __syncthreads();
    ull* sYr = reg2u;
    ull* sYi = reg2u + 1152;

    int hp = t >> 3;                      // 0..31
    int kg = t & 7;                       // k2 group of 4 (2 ull)
    int hA = g0 + hp;
    ull ze0r[2], ze0i[2], zo0r[2], zo0i[2];   // h = hA
    ull ze1r[2], ze1i[2], zo1r[2], zo1i[2];   // h = hA+32
#pragma unroll
    for (int q = 0; q < 2; q++) {
        ze0r[q]=0ull; ze0i[q]=0ull; zo0r[q]=0ull; zo0i[q]=0ull;
        ze1r[q]=0ull; ze1i[q]=0ull; zo1r[q]=0ull; zo1i[q]=0ull;
    }

    // pair a: Zr += c*Er - sin*Oi = c*Er + sti*Oi ; Zi += c*Ei + sin*Or = c*Ei - sti*Or
#define PBODY(A, R0, I0, R1, I1) { \
    int ia = ((A) * hA) & 255; \
    int ib = (ia + (A) * 32) & 255; \
    float c0 = str[ia], t0 = sti[ia]; \
    float c1 = str[ib], t1 = sti[ib]; \
    ull c0p = pk2(c0, c0), t0p = pk2(t0, t0), n0p = pk2(-t0, -t0); \
    ull c1p = pk2(c1, c1), t1p = pk2(t1, t1), n1p = pk2(-t1, -t1); \
    ulonglong2 er  = *(const ulonglong2*)(sYr + (A) * 18 + kg * 2); \
    ulonglong2 ei  = *(const ulonglong2*)(sYi + (A) * 18 + kg * 2); \
    ulonglong2 orr = *(const ulonglong2*)(sYr + (64 - (A)) * 18 + kg * 2); \
    ulonglong2 oii = *(const ulonglong2*)(sYi + (64 - (A)) * 18 + kg * 2); \
    R0[0] = ffma2(er.x, c0p, R0[0]);  R0[0] = ffma2(oii.x, t0p, R0[0]); \
    I0[0] = ffma2(ei.x, c0p, I0[0]);  I0[0] = ffma2(orr.x, n0p, I0[0]); \
    R0[1] = ffma2(er.y, c0p, R0[1]);  R0[1] = ffma2(oii.y, t0p, R0[1]); \
    I0[1] = ffma2(ei.y, c0p, I0[1]);  I0[1] = ffma2(orr.y, n0p, I0[1]); \
    R1[0] = ffma2(er.x, c1p, R1[0]);  R1[0] = ffma2(oii.x, t1p, R1[0]); \
    I1[0] = ffma2(ei.x, c1p, I1[0]);  I1[0] = ffma2(orr.x, n1p, I1[0]); \
    R1[1] = ffma2(er.y, c1p, R1[1]);  R1[1] = ffma2(oii.y, t1p, R1[1]); \
    I1[1] = ffma2(ei.y, c1p, I1[1]);  I1[1] = ffma2(orr.y, n1p, I1[1]); }

#pragma unroll 3
    for (int ap = 0; ap < 15; ap++) {
        PBODY(2 * ap + 1, zo0r, zo0i, zo1r, zo1i)
        PBODY(2 * ap + 2, ze0r, ze0i, ze1r, ze1i)
    }
    PBODY(31, zo0r, zo0i, zo1r, zo1i)
#undef PBODY

    {   // j=0 (k1=0, even): constant contribution Y0 to both h regs
        ulonglong2 y0r = *(const ulonglong2*)(sYr + kg * 2);
        ulonglong2 y0i = *(const ulonglong2*)(sYi + kg * 2);
        ze0r[0] = add2(ze0r[0], y0r.x); ze0r[1] = add2(ze0r[1], y0r.y);
        ze0i[0] = add2(ze0i[0], y0i.x); ze0i[1] = add2(ze0i[1], y0i.y);
        ze1r[0] = add2(ze1r[0], y0r.x); ze1r[1] = add2(ze1r[1], y0r.y);
        ze1i[0] = add2(ze1i[0], y0i.x); ze1i[1] = add2(ze1i[1], y0i.y);
    }
    {   // j=32 (k1=-32, even): e^{-i32h} -- same angle for hA and hA+32
        int i32 = (32 * hA) & 255;
        float c = str[i32], tv = sti[i32];
        ull cp = pk2(c, c), tp = pk2(tv, tv), np = pk2(-tv, -tv);
        ulonglong2 y2r = *(const ulonglong2*)(sYr + 32 * 18 + kg * 2);
        ulonglong2 y2i = *(const ulonglong2*)(sYi + 32 * 18 + kg * 2);
        // Zr += c*Y32r - sti*Y32i ; Zi += c*Y32i + sti*Y32r
#pragma unroll
        for (int q = 0; q < 2; q++) {
            ull r2v = q ? y2r.y : y2r.x;
            ull i2v = q ? y2i.y : y2i.x;
            ze0r[q] = ffma2(r2v, cp, ze0r[q]);  ze0r[q] = ffma2(i2v, np, ze0r[q]);
            ze0i[q] = ffma2(i2v, cp, ze0i[q]);  ze0i[q] = ffma2(r2v, tp, ze0i[q]);
            ze1r[q] = ffma2(r2v, cp, ze1r[q]);  ze1r[q] = ffma2(i2v, np, ze1r[q]);
            ze1i[q] = ffma2(i2v, cp, ze1i[q]);  ze1i[q] = ffma2(r2v, tp, ze1i[q]);
        }
    }

    // combine parity partials -> both h tiles
    {
        const ull M1 = pk2(-1.f, -1.f);
#pragma unroll
        for (int q = 0; q < 2; q++) {
            int c2 = 2 * (kg * 4 + 2 * q);
            float2 ra, ia, rb, ib;
            ra = upk(add2(ze0r[q], zo0r[q]));  ia = upk(add2(ze0i[q], zo0i[q]));
            rb = upk(ffma2(zo0r[q], M1, ze0r[q]));  ib = upk(ffma2(zo0i[q], M1, ze0i[q]));
            zsA[c2 * 68 + hp]       = ra.x; zsA[(c2 + 1) * 68 + hp] = ia.x;
            zsA[(c2 + 2) * 68 + hp] = ra.y; zsA[(c2 + 3) * 68 + hp] = ia.y;
            zsB[c2 * 68 + hp]       = rb.x; zsB[(c2 + 1) * 68 + hp] = ib.x;
            zsB[(c2 + 2) * 68 + hp] = rb.y; zsB[(c2 + 3) * 68 + hp] = ib.y;
            ra = upk(add2(ze1r[q], zo1r[q]));  ia = upk(add2(ze1i[q], zo1i[q]));
            rb = upk(ffma2(zo1r[q], M1, ze1r[q]));  ib = upk(ffma2(zo1i[q], M1, ze1i[q]));
            zsA[c2 * 68 + hp + 32]       = ra.x; zsA[(c2 + 1) * 68 + hp + 32] = ia.x;
            zsA[(c2 + 2) * 68 + hp + 32] = ra.y; zsA[(c2 + 3) * 68 + hp + 32] = ia.y;
            zsB[c2 * 68 + hp + 32]       = rb.x; zsB[(c2 + 1) * 68 + hp + 32] = ib.x;
            zsB[(c2 + 2) * 68 + hp + 32] = rb.y; zsB[(c2 + 3) * 68 + hp + 32] = ib.y;
        }
    }
    __syncthreads();

    // w=128 columns for both tiles
    if (t < 128) {
        int tile = t >> 6;
        int row  = t & 63;
        const float* zz = tile ? zsB : zsA;
        float s = zz[row];
#pragma unroll
        for (int k2 = 1; k2 < 32; k2++)
            s += ((k2 & 1) ? -2.f : 2.f) * zz[2 * k2 * 68 + row];
        out[((size_t)ch * 256 + g0 + tile * 128 + row) * 256 + 128] = s * (1.f / 65536.f);
    }

    // Phase B: folded inverse-w on both tiles
    int hg = t >> 4;                      // 0..15 -> 4 h rows
    int wg = t & 15;                      // 4 w' cols
    const float4* FcG = (const float4*)g_Fc;
    const float4* FsG = (const float4*)g_Fs;
    const ull M1 = pk2(-1.f, -1.f);
    for (int wt = 0; wt < 2; wt++) {
        __syncthreads();
        float4* fd = (float4*)reg2;
#pragma unroll
        for (int q = 0; q < 2; q++) {
            int flat = q * 256 + t;
            int k2 = flat >> 4, u = flat & 15;
            fd[k2 * 16 + u]       = FcG[k2 * 32 + wt * 16 + u];
            fd[512 + k2 * 16 + u] = FsG[k2 * 32 + wt * 16 + u];
        }
        __syncthreads();
        for (int tile = 0; tile < 2; tile++) {
            const float* zs = tile ? zsB : zsA;
            int hbase = g0 + tile * 128;
            ull P[8], Q[8];
#pragma unroll
            for (int q = 0; q < 8; q++) { P[q] = 0ull; Q[q] = 0ull; }
#pragma unroll 4
            for (int k2 = 0; k2 < 32; k2++) {
                float4 a = *(const float4*)(zs + (2 * k2) * 68 + hg * 4);
                float4 b = *(const float4*)(zs + (2 * k2 + 1) * 68 + hg * 4);
                const float* fp = reg2 + k2 * 64 + wg * 4;
                ulonglong2 f = *(const ulonglong2*)fp;
                ulonglong2 g = *(const ulonglong2*)(fp + 2048);
                ull pr, pi;
#define BROW(R, AV, BV) \
                pr = pk2(AV, AV); pi = pk2(BV, BV); \
                P[R*2+0] = ffma2(pr, f.x, P[R*2+0]); P[R*2+1] = ffma2(pr, f.y, P[R*2+1]); \
                Q[R*2+0] = ffma2(pi, g.x, Q[R*2+0]); Q[R*2+1] = ffma2(pi, g.y, Q[R*2+1]);
                BROW(0, a.x, b.x) BROW(1, a.y, b.y) BROW(2, a.z, b.z) BROW(3, a.w, b.w)
#undef BROW
            }
#pragma unroll
            for (int r = 0; r < 4; r++) {
                int hloc = hg * 4 + r;
                float* orow = out + ((size_t)ch * 256 + hbase + hloc) * 256;
                int wbase = wt * 64 + wg * 4;
                ull A0 = add2(P[r * 2], Q[r * 2]);
                ull A1 = add2(P[r * 2 + 1], Q[r * 2 + 1]);
                ull B0 = ffma2(Q[r * 2], M1, P[r * 2]);
                ull B1 = ffma2(Q[r * 2 + 1], M1, P[r * 2 + 1]);
                float2 fa0 = upk(A0), fa1 = upk(A1);
                float2 fb0 = upk(B0), fb1 = upk(B1);
                *(float4*)(orow + wbase) = make_float4(fa0.x, fa0.y, fa1.x, fa1.y);
                float bw[4] = {fb0.x, fb0.y, fb1.x, fb1.y};
#pragma unroll
                for (int i = 0; i < 4; i++) {
                    int wv = wbase + i;
                    if (wv) orow[256 - wv] = bw[i];
                }
            }
        }
    }
}

// ---------------------------------------------------------------------------
extern "C" void kernel_launch(void* const* d_in, const int* in_sizes, int n_in,
                              void* d_out, int out_size) {
    const float* x   = (const float*)d_in[0];
    const float* w1r = (const float*)d_in[1];
    const float* w1i = (const float*)d_in[2];
    const float* w2r = (const float*)d_in[3];
    const float* w2i = (const float*)d_in[4];
    const float* w3r = (const float*)d_in[5];
    const float* w3i = (const float*)d_in[6];
    const float* w4r = (const float*)d_in[7];
    const float* w4i = (const float*)d_in[8];
    float* out = (float*)d_out;

    k_init<<<34, 256>>>();

    // ---- branch x ----
    k_s1s2<<<512, 256>>>(x, 0);
    k_s3<<<512, 256>>>(w1r, w1i, w2r, w2i);
    k_s4s5<<<1024, 256>>>(out);

    // ---- branch x^T ----
    k_s1s2<<<512, 256>>>(x, 1);
    k_s3<<<512, 256>>>(w3r, w3i, w4r, w4i);
    k_s4s5<<<1024, 256>>>(out + (size_t)NCH * 65536);
}